// round 14
// baseline (speedup 1.0000x reference)
#include <cuda_runtime.h>
#include <cuda_fp16.h>
#include <cstdint>
#include <math.h>

// ---------------------------------------------------------------------------
// Model dims
// ---------------------------------------------------------------------------
#define BATCH 4096
#define SEQ   48
#define DEMB  300
#define DHID  512
#define NGATE 2048           // 4*DHID
#define KREAL 812            // DEMB + DHID
#define KPAD  832            // 13 chunks of 64
#define M2    8192           // 2*BATCH
#define FIN   1025           // 2*DHID + 1
#define DOUT  3

#define BK      64
#define NCHUNK  13           // KPAD/BK, single fp16 product
#define NSTAGE  3
#define BM      64
#define BN      128
#define A_BYTES 8192         // 64 rows x 128B
#define B_BYTES 16384        // 128 rows x 128B
#define STAGE_BYTES (A_BYTES + B_BYTES)       // 24576
#define SMEM_DYN   (NSTAGE * STAGE_BYTES)     // 73728

// MLP dims (fp16 3-product path)
#define KP2    1088          // FIN padded to 17 chunks of 64
#define NMLP   51            // 3 plane-products
#define NPAD   1152          // 9 * BN (N=1025 padded)

// ---------------------------------------------------------------------------
// Device scratch (static only)
// ---------------------------------------------------------------------------
__device__ __half d_X[2][(size_t)M2 * KPAD];
__device__ __half d_W[(size_t)NGATE * KPAD];
__device__ float d_bias[NGATE];
__device__ float d_cbuf[(size_t)M2 * DHID];
__device__ float d_x0[BATCH * FIN];
__device__ float d_x1[BATCH * FIN];
__device__ float d_x2[BATCH * FIN];
__device__ float d_scale[FIN];
__device__ float d_shift[FIN];
// MLP fp16 planes
__device__ __half d_W0hi[(size_t)NPAD * KP2];
__device__ __half d_W0lo[(size_t)NPAD * KP2];
__device__ __half d_W1hi[(size_t)NPAD * KP2];
__device__ __half d_W1lo[(size_t)NPAD * KP2];
__device__ __half d_mAhi[(size_t)BATCH * KP2];
__device__ __half d_mAlo[(size_t)BATCH * KP2];

// ---------------------------------------------------------------------------
// PTX helpers
// ---------------------------------------------------------------------------
__device__ __forceinline__ uint32_t smem_u32(const void* p) {
    uint32_t a;
    asm("{ .reg .u64 t; cvta.to.shared.u64 t, %1; cvt.u32.u64 %0, t; }" : "=r"(a) : "l"(p));
    return a;
}
__device__ __forceinline__ void cp16(uint32_t s, const void* g) {
    asm volatile("cp.async.cg.shared.global [%0], [%1], 16;" :: "r"(s), "l"(g));
}
#define CP_COMMIT() asm volatile("cp.async.commit_group;" ::: "memory")
#define CP_WAIT1()  asm volatile("cp.async.wait_group 1;" ::: "memory")

#define LDSM_X4(r0, r1, r2, r3, addr) \
    asm volatile("ldmatrix.sync.aligned.m8n8.x4.shared.b16 {%0,%1,%2,%3}, [%4];" \
        : "=r"(r0), "=r"(r1), "=r"(r2), "=r"(r3) : "r"(addr))

__device__ __forceinline__ void mma16816(float c[4], const uint32_t a[4], const uint32_t b[2]) {
    asm volatile(
        "mma.sync.aligned.m16n8k16.row.col.f32.f16.f16.f32 "
        "{%0,%1,%2,%3}, {%4,%5,%6,%7}, {%8,%9}, {%0,%1,%2,%3};"
        : "+f"(c[0]), "+f"(c[1]), "+f"(c[2]), "+f"(c[3])
        : "r"(a[0]), "r"(a[1]), "r"(a[2]), "r"(a[3]), "r"(b[0]), "r"(b[1]));
}

// swizzled byte offset within a [rows x 64 fp16] tile (128B rows)
__device__ __forceinline__ uint32_t swz(int row, int c16) {
    return (uint32_t)(row * 128 + ((c16 ^ (row & 7)) << 4));
}

__device__ __forceinline__ float sigmoidf_(float x) { return 1.0f / (1.0f + __expf(-x)); }
__device__ __forceinline__ float tanhf_(float x) {
    x = fminf(15.0f, fmaxf(-15.0f, x));
    float t = __expf(2.0f * x);
    return (t - 1.0f) / (t + 1.0f);
}

// ---------------------------------------------------------------------------
// Build W plane (gate-interleaved rows n'=4*hid+gate, fp16 rn) + bias
// ---------------------------------------------------------------------------
__global__ void __launch_bounds__(256) build_w_kernel(
    const float* __restrict__ Wih, const float* __restrict__ Whh,
    const float* __restrict__ bih, const float* __restrict__ bhh)
{
    int idx = blockIdx.x * 256 + threadIdx.x;
    if (idx >= NGATE * KPAD) return;
    int n = idx / KPAD, k = idx - n * KPAD;
    int gate = n & 3, hid = n >> 2;
    int no = gate * DHID + hid;
    float v = 0.0f;
    if (k < DEMB)       v = Wih[(size_t)no * DEMB + k];
    else if (k < KREAL) v = Whh[(size_t)no * DHID + (k - DEMB)];
    d_W[idx] = __float2half_rn(v);
    if (k == 0) d_bias[n] = bih[no] + bhh[no];
}

// ---------------------------------------------------------------------------
// Build MLP W hi/lo planes, padded [NPAD][KP2]
// ---------------------------------------------------------------------------
__global__ void __launch_bounds__(256) build_mlp_w_kernel(
    const float* __restrict__ W, int layer)
{
    int idx = blockIdx.x * 256 + threadIdx.x;
    if (idx >= NPAD * KP2) return;
    int n = idx / KP2, k = idx - n * KP2;
    float v = (n < FIN && k < FIN) ? W[(size_t)n * FIN + k] : 0.0f;
    __half hi = __float2half_rn(v);
    __half lo = __float2half_rn(v - __half2float(hi));
    if (layer == 0) { d_W0hi[idx] = hi; d_W0lo[idx] = lo; }
    else            { d_W1hi[idx] = hi; d_W1lo[idx] = lo; }
}

__global__ void zero_state_kernel()
{
    size_t stride = (size_t)gridDim.x * blockDim.x;
    size_t nX = (size_t)M2 * KPAD;
    __half z = __float2half_rn(0.0f);
    for (size_t j = blockIdx.x * (size_t)blockDim.x + threadIdx.x; j < nX; j += stride) {
        d_X[0][j] = z;
        d_X[1][j] = z;
    }
    for (size_t j = blockIdx.x * (size_t)blockDim.x + threadIdx.x; j < (size_t)M2 * DHID; j += stride)
        d_cbuf[j] = 0.0f;
}

// ---------------------------------------------------------------------------
// Embedding gather into X[par] cols [0,300) for one step (used for s=0 seed)
// ---------------------------------------------------------------------------
__global__ void __launch_bounds__(256) gather_kernel(
    const float* __restrict__ embed, const int* __restrict__ prem,
    const int* __restrict__ hyp, int s, int par)
{
    int idx = blockIdx.x * 256 + threadIdx.x;          // M2 * 75
    if (idx >= M2 * (DEMB / 4)) return;
    int row = idx / (DEMB / 4), k4 = idx - row * (DEMB / 4);
    int k = k4 * 4;
    int b = row & (BATCH - 1);
    int tok = (row < BATCH) ? prem[s * BATCH + b] : hyp[s * BATCH + b];
    float4 v = *reinterpret_cast<const float4*>(embed + (size_t)tok * DEMB + k);
    __half* xh = &d_X[par][(size_t)row * KPAD + k];
    xh[0] = __float2half_rn(v.x);
    xh[1] = __float2half_rn(v.y);
    xh[2] = __float2half_rn(v.z);
    xh[3] = __float2half_rn(v.w);
}

// ---------------------------------------------------------------------------
// LSTM step via mma.sync fp16 (single product) + fused cell epilogue.
// Tile 64x128, BK=64, 13 chunks, 3-stage cp.async, 3 CTAs/SM.
// bn==0 tiles additionally gather step-(s_next) embeddings into X[par^1].
// ---------------------------------------------------------------------------
__device__ __forceinline__ void load_tileA(uint32_t sbase, const __half* g,
                                           int row0, int k0, int rs, int tid)
{
    int r = tid >> 3;          // 0..31
    int c16 = tid & 7;
    const __half* gp = g + (size_t)(row0 + r) * rs + k0 + c16 * 8;
    #pragma unroll
    for (int p = 0; p < 2; p++)
        cp16(sbase + swz(r + p * 32, c16), gp + (size_t)(p * 32) * rs);
}
__device__ __forceinline__ void load_tileB(uint32_t sbase, const __half* g,
                                           int row0, int k0, int rs, int tid)
{
    int r = tid >> 3;
    int c16 = tid & 7;
    const __half* gp = g + (size_t)(row0 + r) * rs + k0 + c16 * 8;
    #pragma unroll
    for (int p = 0; p < 4; p++)
        cp16(sbase + swz(r + p * 32, c16), gp + (size_t)(p * 32) * rs);
}

__global__ void __launch_bounds__(256, 3) lstm_mma_kernel(
    int par, int s_next, const float* __restrict__ embed,
    const int* __restrict__ prem, const int* __restrict__ hyp)
{
    extern __shared__ char smem[];
    uint32_t sbase = smem_u32(smem);
    int tid = threadIdx.x;
    int wid = tid >> 5, lane = tid & 31;
    int wm = wid >> 2, wn = wid & 3;          // 2 x 4 warp grid; warp tile 32x32
    int bn = blockIdx.x * BN;                 // N (gate) tile
    int bm = blockIdx.y * BM;                 // M (row) tile

    const __half* X_r = d_X[par];
    __half* X_w = d_X[par ^ 1];

    float acc[2][4][4] = {};

    auto issue_chunk = [&](int kc, int stage) {
        uint32_t sA = sbase + stage * STAGE_BYTES;
        uint32_t sB = sA + A_BYTES;
        load_tileA(sA, X_r, bm, kc * BK, KPAD, tid);
        load_tileB(sB, d_W, bn, kc * BK, KPAD, tid);
    };

    issue_chunk(0, 0); CP_COMMIT();
    issue_chunk(1, 1); CP_COMMIT();

    for (int c = 0; c < NCHUNK; c++) {
        CP_WAIT1();
        __syncthreads();
        int stage = c % NSTAGE;
        uint32_t sA = sbase + stage * STAGE_BYTES;
        uint32_t sB = sA + A_BYTES;

        #pragma unroll
        for (int ks = 0; ks < 4; ks++) {
            uint32_t a[2][4];
            #pragma unroll
            for (int mt = 0; mt < 2; mt++) {
                int row = wm * 32 + mt * 16 + (lane & 15);
                int c16 = ks * 2 + (lane >> 4);
                LDSM_X4(a[mt][0], a[mt][1], a[mt][2], a[mt][3], sA + swz(row, c16));
            }
            uint32_t b[4][2];
            #pragma unroll
            for (int nt2 = 0; nt2 < 2; nt2++) {
                int rown = wn * 32 + nt2 * 16 + (lane & 7) + (((lane >> 4) & 1) << 3);
                int c16 = ks * 2 + ((lane >> 3) & 1);
                uint32_t r0, r1, r2, r3;
                LDSM_X4(r0, r1, r2, r3, sB + swz(rown, c16));
                b[nt2 * 2][0] = r0;  b[nt2 * 2][1] = r1;
                b[nt2 * 2 + 1][0] = r2;  b[nt2 * 2 + 1][1] = r3;
            }
            #pragma unroll
            for (int mt = 0; mt < 2; mt++)
                #pragma unroll
                for (int nt = 0; nt < 4; nt++)
                    mma16816(acc[mt][nt], a[mt], b[nt]);
        }

        int nc = c + NSTAGE - 1;
        if (nc < NCHUNK) issue_chunk(nc, nc % NSTAGE);
        CP_COMMIT();
    }

    // ---- write accs to SMEM (reuse pipeline buffers) ----
    __syncthreads();
    float* Cs = (float*)smem;          // [64][132]
    #pragma unroll
    for (int mt = 0; mt < 2; mt++)
        #pragma unroll
        for (int nt = 0; nt < 4; nt++) {
            int r = wm * 32 + mt * 16 + (lane >> 2);
            int col = wn * 32 + nt * 8 + (lane & 3) * 2;
            Cs[r * 132 + col]           = acc[mt][nt][0];
            Cs[r * 132 + col + 1]       = acc[mt][nt][1];
            Cs[(r + 8) * 132 + col]     = acc[mt][nt][2];
            Cs[(r + 8) * 132 + col + 1] = acc[mt][nt][3];
        }
    __syncthreads();

    // ---- fused LSTM cell: 64 rows x 32 quads = 2048 items, 8 per thread ----
    #pragma unroll
    for (int i = 0; i < 8; i++) {
        int id = i * 256 + tid;
        int r = id >> 5, q = id & 31;
        int m = bm + r;
        int col = bn + q * 4;
        int hid = col >> 2;
        const float* cr = &Cs[r * 132 + q * 4];
        float ig = cr[0] + d_bias[col + 0];
        float fg = cr[1] + d_bias[col + 1];
        float gg = cr[2] + d_bias[col + 2];
        float og = cr[3] + d_bias[col + 3];
        size_t ci = (size_t)m * DHID + hid;
        float cn = sigmoidf_(fg) * d_cbuf[ci] + sigmoidf_(ig) * tanhf_(gg);
        float hn = sigmoidf_(og) * tanhf_(cn);
        d_cbuf[ci] = cn;
        X_w[(size_t)m * KPAD + DEMB + hid] = __float2half_rn(hn);
    }

    // ---- fused gather: bn==0 tiles write step-(s_next) embeddings for
    //      rows [bm, bm+64) into X_w cols [0,300).  Consumer = next launch.
    if (bn == 0 && s_next < SEQ) {
        for (int i = tid; i < BM * (DEMB / 4); i += 256) {
            int r = i / (DEMB / 4), k4 = i - r * (DEMB / 4);
            int row = bm + r;
            int b = row & (BATCH - 1);
            int tok = (row < BATCH) ? prem[s_next * BATCH + b]
                                    : hyp[s_next * BATCH + b];
            float4 v = *reinterpret_cast<const float4*>(
                embed + (size_t)tok * DEMB + k4 * 4);
            __half* xh = &X_w[(size_t)row * KPAD + k4 * 4];
            xh[0] = __float2half_rn(v.x);
            xh[1] = __float2half_rn(v.y);
            xh[2] = __float2half_rn(v.z);
            xh[3] = __float2half_rn(v.w);
        }
    }
}

// ---------------------------------------------------------------------------
// Cosine distance + assemble x0 = [dist, p, h] (reads X[0])
// ---------------------------------------------------------------------------
__global__ void cosine_assemble_kernel()
{
    int warp = (blockIdx.x * blockDim.x + threadIdx.x) >> 5;
    int lane = threadIdx.x & 31;
    if (warp >= BATCH) return;
    const __half* ph = d_X[0] + (size_t)warp * KPAD + DEMB;
    const __half* hh = d_X[0] + (size_t)(BATCH + warp) * KPAD + DEMB;
    float dot = 0, np = 0, nh = 0;
    for (int k = lane; k < DHID; k += 32) {
        float a = __half2float(ph[k]);
        float b = __half2float(hh[k]);
        dot += a * b; np += a * a; nh += b * b;
        d_x0[(size_t)warp * FIN + 1 + k]        = a;
        d_x0[(size_t)warp * FIN + 1 + DHID + k] = b;
    }
    #pragma unroll
    for (int o = 16; o; o >>= 1) {
        dot += __shfl_xor_sync(0xffffffffu, dot, o);
        np  += __shfl_xor_sync(0xffffffffu, np,  o);
        nh  += __shfl_xor_sync(0xffffffffu, nh,  o);
    }
    if (lane == 0)
        d_x0[(size_t)warp * FIN] = 1.0f - dot / (sqrtf(np) * sqrtf(nh));
}

// ---------------------------------------------------------------------------
// BatchNorm stats -> folded scale/shift
// ---------------------------------------------------------------------------
__global__ void bn_stats_kernel(int which, const float* __restrict__ gamma,
                                const float* __restrict__ beta, int M, int F)
{
    const float* x = (which == 0) ? d_x0 : (which == 1) ? d_x1 : d_x2;
    __shared__ float s1[8][33];
    int fl = threadIdx.x & 31;
    int f  = blockIdx.x * 32 + fl;
    int rl = threadIdx.x >> 5;

    float s = 0;
    if (f < F) for (int r = rl; r < M; r += 8) s += x[(size_t)r * F + f];
    s1[rl][fl] = s;
    __syncthreads();
    if (rl == 0) {
        float t = 0;
        #pragma unroll
        for (int i = 0; i < 8; i++) t += s1[i][fl];
        s1[0][fl] = t / (float)M;
    }
    __syncthreads();
    float mean = s1[0][fl];
    __syncthreads();

    float v = 0;
    if (f < F) for (int r = rl; r < M; r += 8) {
        float d = x[(size_t)r * F + f] - mean;
        v += d * d;
    }
    s1[rl][fl] = v;
    __syncthreads();
    if (rl == 0 && f < F) {
        float t = 0;
        #pragma unroll
        for (int i = 0; i < 8; i++) t += s1[i][fl];
        float rstd = rsqrtf(t / (float)M + 1e-5f);
        float sc = rstd * gamma[f];
        d_scale[f] = sc;
        d_shift[f] = beta[f] - mean * sc;
    }
}

// ---------------------------------------------------------------------------
// Convert BN(x) to fp16 hi/lo planes [BATCH][KP2]
// ---------------------------------------------------------------------------
__global__ void __launch_bounds__(256) bnconv_kernel(int which)
{
    const float* x = (which == 0) ? d_x0 : (which == 1) ? d_x1 : d_x2;
    int idx = blockIdx.x * 256 + threadIdx.x;
    if (idx >= BATCH * KP2) return;
    int m = idx / KP2, k = idx - m * KP2;
    float y = 0.0f;
    if (k < FIN) y = x[(size_t)m * FIN + k] * d_scale[k] + d_shift[k];
    __half hi = __float2half_rn(y);
    d_mAhi[idx] = hi;
    d_mAlo[idx] = __float2half_rn(y - __half2float(hi));
}

// ---------------------------------------------------------------------------
// MLP hidden layer: out = relu( BN(x) @ W^T + bl ) via fp16 3-product mma.
// ---------------------------------------------------------------------------
__global__ void __launch_bounds__(256, 3) mlp_mma_kernel(
    int layer, const float* __restrict__ bl)
{
    extern __shared__ char smem[];
    uint32_t sbase = smem_u32(smem);
    int tid = threadIdx.x;
    int wid = tid >> 5, lane = tid & 31;
    int wm = wid >> 2, wn = wid & 3;
    int bn = blockIdx.x * BN;
    int bm = blockIdx.y * BM;

    const __half* Whi = layer ? d_W1hi : d_W0hi;
    const __half* Wlo = layer ? d_W1lo : d_W0lo;
    float* out = layer ? d_x2 : d_x1;

    float acc[2][4][4] = {};

    // chunk c: 0..16 Ahi*Whi, 17..33 Ahi*Wlo, 34..50 Alo*Whi
    auto issue_chunk = [&](int c, int stage) {
        const __half* A = (c < 34) ? d_mAhi : d_mAlo;
        const __half* B = (c >= 17 && c < 34) ? Wlo : Whi;
        int kc = (c < 17) ? c : (c < 34) ? c - 17 : c - 34;
        uint32_t sA = sbase + stage * STAGE_BYTES;
        uint32_t sB = sA + A_BYTES;
        load_tileA(sA, A, bm, kc * BK, KP2, tid);
        load_tileB(sB, B, bn, kc * BK, KP2, tid);
    };

    issue_chunk(0, 0); CP_COMMIT();
    issue_chunk(1, 1); CP_COMMIT();

    for (int c = 0; c < NMLP; c++) {
        CP_WAIT1();
        __syncthreads();
        int stage = c % NSTAGE;
        uint32_t sA = sbase + stage * STAGE_BYTES;
        uint32_t sB = sA + A_BYTES;

        #pragma unroll
        for (int ks = 0; ks < 4; ks++) {
            uint32_t a[2][4];
            #pragma unroll
            for (int mt = 0; mt < 2; mt++) {
                int row = wm * 32 + mt * 16 + (lane & 15);
                int c16 = ks * 2 + (lane >> 4);
                LDSM_X4(a[mt][0], a[mt][1], a[mt][2], a[mt][3], sA + swz(row, c16));
            }
            uint32_t b[4][2];
            #pragma unroll
            for (int nt2 = 0; nt2 < 2; nt2++) {
                int rown = wn * 32 + nt2 * 16 + (lane & 7) + (((lane >> 4) & 1) << 3);
                int c16 = ks * 2 + ((lane >> 3) & 1);
                uint32_t r0, r1, r2, r3;
                LDSM_X4(r0, r1, r2, r3, sB + swz(rown, c16));
                b[nt2 * 2][0] = r0;  b[nt2 * 2][1] = r1;
                b[nt2 * 2 + 1][0] = r2;  b[nt2 * 2 + 1][1] = r3;
            }
            #pragma unroll
            for (int mt = 0; mt < 2; mt++)
                #pragma unroll
                for (int nt = 0; nt < 4; nt++)
                    mma16816(acc[mt][nt], a[mt], b[nt]);
        }

        int nc = c + NSTAGE - 1;
        if (nc < NMLP) issue_chunk(nc, nc % NSTAGE);
        CP_COMMIT();
    }

    // ---- write accs to SMEM ----
    __syncthreads();
    float* Cs = (float*)smem;          // [64][132]
    #pragma unroll
    for (int mt = 0; mt < 2; mt++)
        #pragma unroll
        for (int nt = 0; nt < 4; nt++) {
            int r = wm * 32 + mt * 16 + (lane >> 2);
            int col = wn * 32 + nt * 8 + (lane & 3) * 2;
            Cs[r * 132 + col]           = acc[mt][nt][0];
            Cs[r * 132 + col + 1]       = acc[mt][nt][1];
            Cs[(r + 8) * 132 + col]     = acc[mt][nt][2];
            Cs[(r + 8) * 132 + col + 1] = acc[mt][nt][3];
        }
    __syncthreads();

    // ---- bias + relu + store fp32 (guard n < FIN) ----
    #pragma unroll
    for (int i = 0; i < 8; i++) {
        int id = i * 256 + tid;
        int r = id >> 5, q = id & 31;
        int m = bm + r;
        int col = bn + q * 4;
        const float* cr = &Cs[r * 132 + q * 4];
        #pragma unroll
        for (int j = 0; j < 4; j++) {
            int n = col + j;
            if (n < FIN)
                out[(size_t)m * FIN + n] = fmaxf(cr[j] + bl[n], 0.0f);
        }
    }
}

__global__ void final_linear_kernel(const float* __restrict__ Wo,
                                    const float* __restrict__ blo,
                                    float* __restrict__ out)
{
    int m = blockIdx.x;
    int tid = threadIdx.x;  // 128
    float a0 = 0, a1 = 0, a2 = 0;
    for (int k = tid; k < FIN; k += 128) {
        float v = d_x2[(size_t)m * FIN + k] * d_scale[k] + d_shift[k];
        a0 += v * Wo[k];
        a1 += v * Wo[FIN + k];
        a2 += v * Wo[2 * FIN + k];
    }
    #pragma unroll
    for (int o = 16; o; o >>= 1) {
        a0 += __shfl_xor_sync(0xffffffffu, a0, o);
        a1 += __shfl_xor_sync(0xffffffffu, a1, o);
        a2 += __shfl_xor_sync(0xffffffffu, a2, o);
    }
    __shared__ float sm[3][4];
    int w = tid >> 5, lane = tid & 31;
    if (lane == 0) { sm[0][w] = a0; sm[1][w] = a1; sm[2][w] = a2; }
    __syncthreads();
    if (tid == 0) {
        out[m * 3 + 0] = sm[0][0] + sm[0][1] + sm[0][2] + sm[0][3] + blo[0];
        out[m * 3 + 1] = sm[1][0] + sm[1][1] + sm[1][2] + sm[1][3] + blo[1];
        out[m * 3 + 2] = sm[2][0] + sm[2][1] + sm[2][2] + sm[2][3] + blo[2];
    }
}

// ---------------------------------------------------------------------------
// Host launch
// ---------------------------------------------------------------------------
extern "C" void kernel_launch(void* const* d_in, const int* in_sizes, int n_in,
                              void* d_out, int out_size)
{
    const int*   prem  = (const int*)d_in[0];
    const int*   hyp   = (const int*)d_in[1];
    const float* embed = (const float*)d_in[2];
    const float* Wih   = (const float*)d_in[3];
    const float* Whh   = (const float*)d_in[4];
    const float* bih   = (const float*)d_in[5];
    const float* bhh   = (const float*)d_in[6];
    const float* g0  = (const float*)d_in[7];
    const float* be0 = (const float*)d_in[8];
    const float* W0  = (const float*)d_in[9];
    const float* bl0 = (const float*)d_in[10];
    const float* g1  = (const float*)d_in[11];
    const float* be1 = (const float*)d_in[12];
    const float* W1  = (const float*)d_in[13];
    const float* bl1 = (const float*)d_in[14];
    const float* go  = (const float*)d_in[15];
    const float* beo = (const float*)d_in[16];
    const float* Wo  = (const float*)d_in[17];
    const float* blo = (const float*)d_in[18];
    float* out = (float*)d_out;

    cudaFuncSetAttribute(lstm_mma_kernel,
                         cudaFuncAttributeMaxDynamicSharedMemorySize, SMEM_DYN);
    cudaFuncSetAttribute(mlp_mma_kernel,
                         cudaFuncAttributeMaxDynamicSharedMemorySize, SMEM_DYN);

    build_w_kernel<<<(NGATE * KPAD + 255) / 256, 256>>>(Wih, Whh, bih, bhh);
    build_mlp_w_kernel<<<(NPAD * KP2 + 255) / 256, 256>>>(W0, 0);
    build_mlp_w_kernel<<<(NPAD * KP2 + 255) / 256, 256>>>(W1, 1);
    zero_state_kernel<<<1024, 256>>>();

    // seed step-0 embeddings; steps 1..47 are gathered by the previous step's epilogue
    gather_kernel<<<(M2 * (DEMB / 4) + 255) / 256, 256>>>(embed, prem, hyp, 0, 0);

    for (int s = 0; s < SEQ; s++)
        lstm_mma_kernel<<<dim3(NGATE / BN, M2 / BM), 256, SMEM_DYN>>>(
            s & 1, s + 1, embed, prem, hyp);

    cosine_assemble_kernel<<<512, 256>>>();

    // MLP: (BN -> fp16 GEMM+ReLU) x2 -> BN -> fp32 final
    bn_stats_kernel<<<(FIN + 31) / 32, 256>>>(0, g0, be0, BATCH, FIN);
    bnconv_kernel<<<(BATCH * KP2 + 255) / 256, 256>>>(0);
    mlp_mma_kernel<<<dim3(NPAD / BN, BATCH / BM), 256, SMEM_DYN>>>(0, bl0);
    bn_stats_kernel<<<(FIN + 31) / 32, 256>>>(1, g1, be1, BATCH, FIN);
    bnconv_kernel<<<(BATCH * KP2 + 255) / 256, 256>>>(1);
    mlp_mma_kernel<<<dim3(NPAD / BN, BATCH / BM), 256, SMEM_DYN>>>(1, bl1);
    bn_stats_kernel<<<(FIN + 31) / 32, 256>>>(2, go, beo, BATCH, FIN);
    final_linear_kernel<<<BATCH, 128>>>(Wo, blo, out);
}

// round 15
// speedup vs baseline: 1.0919x; 1.0919x over previous
#include <cuda_runtime.h>
#include <cuda_fp16.h>
#include <cstdint>
#include <math.h>

// ---------------------------------------------------------------------------
// Model dims
// ---------------------------------------------------------------------------
#define BATCH 4096
#define SEQ   48
#define DEMB  300
#define DHID  512
#define NGATE 2048           // 4*DHID
#define KREAL 812            // DEMB + DHID
#define KPAD  832            // 13 chunks of 64
#define M2    8192           // 2*BATCH
#define FIN   1025           // 2*DHID + 1
#define DOUT  3

#define BK      64
#define NCHUNK  13           // KPAD/BK, single fp16 product
#define NSTAGE  3
#define BM      64
#define BN      128
#define A_BYTES 8192         // 64 rows x 128B
#define B_BYTES 16384        // 128 rows x 128B
#define STAGE_BYTES (A_BYTES + B_BYTES)       // 24576
#define SMEM_DYN   (NSTAGE * STAGE_BYTES)     // 73728

// MLP dims (fp16 3-product path)
#define KP2    1088          // FIN padded to 17 chunks of 64
#define NMLP   51            // 3 plane-products
#define NPAD   1152          // 9 * BN (N=1025 padded)

// ---------------------------------------------------------------------------
// Device scratch (static only)
// ---------------------------------------------------------------------------
__device__ __half d_X[2][(size_t)M2 * KPAD];
__device__ __half d_W[(size_t)NGATE * KPAD];
__device__ float d_bias[NGATE];
__device__ float d_cbuf[(size_t)M2 * DHID];
__device__ float d_x0[BATCH * FIN];
__device__ float d_x1[BATCH * FIN];
__device__ float d_x2[BATCH * FIN];
__device__ float d_scale[FIN];
__device__ float d_shift[FIN];
// MLP fp16 planes
__device__ __half d_W0hi[(size_t)NPAD * KP2];
__device__ __half d_W0lo[(size_t)NPAD * KP2];
__device__ __half d_W1hi[(size_t)NPAD * KP2];
__device__ __half d_W1lo[(size_t)NPAD * KP2];
__device__ __half d_mAhi[(size_t)BATCH * KP2];
__device__ __half d_mAlo[(size_t)BATCH * KP2];

// ---------------------------------------------------------------------------
// PTX helpers
// ---------------------------------------------------------------------------
__device__ __forceinline__ uint32_t smem_u32(const void* p) {
    uint32_t a;
    asm("{ .reg .u64 t; cvta.to.shared.u64 t, %1; cvt.u32.u64 %0, t; }" : "=r"(a) : "l"(p));
    return a;
}
__device__ __forceinline__ void cp16(uint32_t s, const void* g) {
    asm volatile("cp.async.cg.shared.global [%0], [%1], 16;" :: "r"(s), "l"(g));
}
#define CP_COMMIT() asm volatile("cp.async.commit_group;" ::: "memory")
#define CP_WAIT1()  asm volatile("cp.async.wait_group 1;" ::: "memory")

#define LDSM_X4(r0, r1, r2, r3, addr) \
    asm volatile("ldmatrix.sync.aligned.m8n8.x4.shared.b16 {%0,%1,%2,%3}, [%4];" \
        : "=r"(r0), "=r"(r1), "=r"(r2), "=r"(r3) : "r"(addr))

__device__ __forceinline__ void mma16816(float c[4], const uint32_t a[4], const uint32_t b[2]) {
    asm volatile(
        "mma.sync.aligned.m16n8k16.row.col.f32.f16.f16.f32 "
        "{%0,%1,%2,%3}, {%4,%5,%6,%7}, {%8,%9}, {%0,%1,%2,%3};"
        : "+f"(c[0]), "+f"(c[1]), "+f"(c[2]), "+f"(c[3])
        : "r"(a[0]), "r"(a[1]), "r"(a[2]), "r"(a[3]), "r"(b[0]), "r"(b[1]));
}

// swizzled byte offset within a [rows x 64 fp16] tile (128B rows)
__device__ __forceinline__ uint32_t swz(int row, int c16) {
    return (uint32_t)(row * 128 + ((c16 ^ (row & 7)) << 4));
}

__device__ __forceinline__ float sigmoidf_(float x) { return 1.0f / (1.0f + __expf(-x)); }
__device__ __forceinline__ float tanhf_(float x) {
    x = fminf(15.0f, fmaxf(-15.0f, x));
    float t = __expf(2.0f * x);
    return (t - 1.0f) / (t + 1.0f);
}

// ---------------------------------------------------------------------------
// Build W plane (gate-interleaved rows n'=4*hid+gate, fp16 rn) + bias
// ---------------------------------------------------------------------------
__global__ void __launch_bounds__(256) build_w_kernel(
    const float* __restrict__ Wih, const float* __restrict__ Whh,
    const float* __restrict__ bih, const float* __restrict__ bhh)
{
    int idx = blockIdx.x * 256 + threadIdx.x;
    if (idx >= NGATE * KPAD) return;
    int n = idx / KPAD, k = idx - n * KPAD;
    int gate = n & 3, hid = n >> 2;
    int no = gate * DHID + hid;
    float v = 0.0f;
    if (k < DEMB)       v = Wih[(size_t)no * DEMB + k];
    else if (k < KREAL) v = Whh[(size_t)no * DHID + (k - DEMB)];
    d_W[idx] = __float2half_rn(v);
    if (k == 0) d_bias[n] = bih[no] + bhh[no];
}

// ---------------------------------------------------------------------------
// Build MLP W hi/lo planes, padded [NPAD][KP2]
// ---------------------------------------------------------------------------
__global__ void __launch_bounds__(256) build_mlp_w_kernel(
    const float* __restrict__ W, int layer)
{
    int idx = blockIdx.x * 256 + threadIdx.x;
    if (idx >= NPAD * KP2) return;
    int n = idx / KP2, k = idx - n * KP2;
    float v = (n < FIN && k < FIN) ? W[(size_t)n * FIN + k] : 0.0f;
    __half hi = __float2half_rn(v);
    __half lo = __float2half_rn(v - __half2float(hi));
    if (layer == 0) { d_W0hi[idx] = hi; d_W0lo[idx] = lo; }
    else            { d_W1hi[idx] = hi; d_W1lo[idx] = lo; }
}

__global__ void zero_state_kernel()
{
    size_t stride = (size_t)gridDim.x * blockDim.x;
    size_t nX = (size_t)M2 * KPAD;
    __half z = __float2half_rn(0.0f);
    for (size_t j = blockIdx.x * (size_t)blockDim.x + threadIdx.x; j < nX; j += stride) {
        d_X[0][j] = z;
        d_X[1][j] = z;
    }
    for (size_t j = blockIdx.x * (size_t)blockDim.x + threadIdx.x; j < (size_t)M2 * DHID; j += stride)
        d_cbuf[j] = 0.0f;
}

// ---------------------------------------------------------------------------
// Embedding gather into X[par] cols [0,300) for one step (s=0 seed)
// ---------------------------------------------------------------------------
__global__ void __launch_bounds__(256) gather_kernel(
    const float* __restrict__ embed, const int* __restrict__ prem,
    const int* __restrict__ hyp, int s, int par)
{
    int idx = blockIdx.x * 256 + threadIdx.x;          // M2 * 75
    if (idx >= M2 * (DEMB / 4)) return;
    int row = idx / (DEMB / 4), k4 = idx - row * (DEMB / 4);
    int k = k4 * 4;
    int b = row & (BATCH - 1);
    int tok = (row < BATCH) ? prem[s * BATCH + b] : hyp[s * BATCH + b];
    float4 v = *reinterpret_cast<const float4*>(embed + (size_t)tok * DEMB + k);
    __half* xh = &d_X[par][(size_t)row * KPAD + k];
    xh[0] = __float2half_rn(v.x);
    xh[1] = __float2half_rn(v.y);
    xh[2] = __float2half_rn(v.z);
    xh[3] = __float2half_rn(v.w);
}

// ---------------------------------------------------------------------------
// LSTM step via mma.sync fp16 (single product) + fused cell epilogue.
// Tile 64x128, BK=64, 13 chunks, 3-stage cp.async, 3 CTAs/SM.
// Each tile gathers step-(s_next) embeddings for ITS OWN 4-row slice of the
// stripe (load-balanced across the 16 bn-tiles).
// ---------------------------------------------------------------------------
__device__ __forceinline__ void load_tileA(uint32_t sbase, const __half* g,
                                           int row0, int k0, int rs, int tid)
{
    int r = tid >> 3;          // 0..31
    int c16 = tid & 7;
    const __half* gp = g + (size_t)(row0 + r) * rs + k0 + c16 * 8;
    #pragma unroll
    for (int p = 0; p < 2; p++)
        cp16(sbase + swz(r + p * 32, c16), gp + (size_t)(p * 32) * rs);
}
__device__ __forceinline__ void load_tileB(uint32_t sbase, const __half* g,
                                           int row0, int k0, int rs, int tid)
{
    int r = tid >> 3;
    int c16 = tid & 7;
    const __half* gp = g + (size_t)(row0 + r) * rs + k0 + c16 * 8;
    #pragma unroll
    for (int p = 0; p < 4; p++)
        cp16(sbase + swz(r + p * 32, c16), gp + (size_t)(p * 32) * rs);
}

__global__ void __launch_bounds__(256, 3) lstm_mma_kernel(
    int par, int s_next, const float* __restrict__ embed,
    const int* __restrict__ prem, const int* __restrict__ hyp)
{
    extern __shared__ char smem[];
    uint32_t sbase = smem_u32(smem);
    int tid = threadIdx.x;
    int wid = tid >> 5, lane = tid & 31;
    int wm = wid >> 2, wn = wid & 3;          // 2 x 4 warp grid; warp tile 32x32
    int bn = blockIdx.x * BN;                 // N (gate) tile
    int bm = blockIdx.y * BM;                 // M (row) tile

    const __half* X_r = d_X[par];
    __half* X_w = d_X[par ^ 1];

    float acc[2][4][4] = {};

    auto issue_chunk = [&](int kc, int stage) {
        uint32_t sA = sbase + stage * STAGE_BYTES;
        uint32_t sB = sA + A_BYTES;
        load_tileA(sA, X_r, bm, kc * BK, KPAD, tid);
        load_tileB(sB, d_W, bn, kc * BK, KPAD, tid);
    };

    issue_chunk(0, 0); CP_COMMIT();
    issue_chunk(1, 1); CP_COMMIT();

    for (int c = 0; c < NCHUNK; c++) {
        CP_WAIT1();
        __syncthreads();
        int stage = c % NSTAGE;
        uint32_t sA = sbase + stage * STAGE_BYTES;
        uint32_t sB = sA + A_BYTES;

        #pragma unroll
        for (int ks = 0; ks < 4; ks++) {
            uint32_t a[2][4];
            #pragma unroll
            for (int mt = 0; mt < 2; mt++) {
                int row = wm * 32 + mt * 16 + (lane & 15);
                int c16 = ks * 2 + (lane >> 4);
                LDSM_X4(a[mt][0], a[mt][1], a[mt][2], a[mt][3], sA + swz(row, c16));
            }
            uint32_t b[4][2];
            #pragma unroll
            for (int nt2 = 0; nt2 < 2; nt2++) {
                int rown = wn * 32 + nt2 * 16 + (lane & 7) + (((lane >> 4) & 1) << 3);
                int c16 = ks * 2 + ((lane >> 3) & 1);
                uint32_t r0, r1, r2, r3;
                LDSM_X4(r0, r1, r2, r3, sB + swz(rown, c16));
                b[nt2 * 2][0] = r0;  b[nt2 * 2][1] = r1;
                b[nt2 * 2 + 1][0] = r2;  b[nt2 * 2 + 1][1] = r3;
            }
            #pragma unroll
            for (int mt = 0; mt < 2; mt++)
                #pragma unroll
                for (int nt = 0; nt < 4; nt++)
                    mma16816(acc[mt][nt], a[mt], b[nt]);
        }

        int nc = c + NSTAGE - 1;
        if (nc < NCHUNK) issue_chunk(nc, nc % NSTAGE);
        CP_COMMIT();
    }

    // ---- write accs to SMEM (reuse pipeline buffers) ----
    __syncthreads();
    float* Cs = (float*)smem;          // [64][132]
    #pragma unroll
    for (int mt = 0; mt < 2; mt++)
        #pragma unroll
        for (int nt = 0; nt < 4; nt++) {
            int r = wm * 32 + mt * 16 + (lane >> 2);
            int col = wn * 32 + nt * 8 + (lane & 3) * 2;
            Cs[r * 132 + col]           = acc[mt][nt][0];
            Cs[r * 132 + col + 1]       = acc[mt][nt][1];
            Cs[(r + 8) * 132 + col]     = acc[mt][nt][2];
            Cs[(r + 8) * 132 + col + 1] = acc[mt][nt][3];
        }
    __syncthreads();

    // ---- fused LSTM cell: 64 rows x 32 quads = 2048 items, 8 per thread ----
    #pragma unroll
    for (int i = 0; i < 8; i++) {
        int id = i * 256 + tid;
        int r = id >> 5, q = id & 31;
        int m = bm + r;
        int col = bn + q * 4;
        int hid = col >> 2;
        const float* cr = &Cs[r * 132 + q * 4];
        float ig = cr[0] + d_bias[col + 0];
        float fg = cr[1] + d_bias[col + 1];
        float gg = cr[2] + d_bias[col + 2];
        float og = cr[3] + d_bias[col + 3];
        size_t ci = (size_t)m * DHID + hid;
        float cn = sigmoidf_(fg) * d_cbuf[ci] + sigmoidf_(ig) * tanhf_(gg);
        float hn = sigmoidf_(og) * tanhf_(cn);
        d_cbuf[ci] = cn;
        X_w[(size_t)m * KPAD + DEMB + hid] = __float2half_rn(hn);
    }

    // ---- fused gather (load-balanced): this tile writes step-(s_next)
    //      embeddings for its own 4-row slice of the stripe.
    //      bn16 = bn/128 in [0,16); rows [bm + bn16*4, bm + bn16*4 + 4).
    if (s_next < SEQ) {
        int r0 = bm + (bn >> 7) * 4;
        for (int i = tid; i < 4 * (DEMB / 4); i += 256) {   // 300 float4
            int r = r0 + i / (DEMB / 4);
            int k4 = i % (DEMB / 4);
            int b = r & (BATCH - 1);
            int tok = (r < BATCH) ? prem[s_next * BATCH + b]
                                  : hyp[s_next * BATCH + b];
            float4 v = *reinterpret_cast<const float4*>(
                embed + (size_t)tok * DEMB + k4 * 4);
            __half* xh = &X_w[(size_t)r * KPAD + k4 * 4];
            xh[0] = __float2half_rn(v.x);
            xh[1] = __float2half_rn(v.y);
            xh[2] = __float2half_rn(v.z);
            xh[3] = __float2half_rn(v.w);
        }
    }
}

// ---------------------------------------------------------------------------
// Cosine distance + assemble x0 = [dist, p, h] (reads X[0])
// ---------------------------------------------------------------------------
__global__ void cosine_assemble_kernel()
{
    int warp = (blockIdx.x * blockDim.x + threadIdx.x) >> 5;
    int lane = threadIdx.x & 31;
    if (warp >= BATCH) return;
    const __half* ph = d_X[0] + (size_t)warp * KPAD + DEMB;
    const __half* hh = d_X[0] + (size_t)(BATCH + warp) * KPAD + DEMB;
    float dot = 0, np = 0, nh = 0;
    for (int k = lane; k < DHID; k += 32) {
        float a = __half2float(ph[k]);
        float b = __half2float(hh[k]);
        dot += a * b; np += a * a; nh += b * b;
        d_x0[(size_t)warp * FIN + 1 + k]        = a;
        d_x0[(size_t)warp * FIN + 1 + DHID + k] = b;
    }
    #pragma unroll
    for (int o = 16; o; o >>= 1) {
        dot += __shfl_xor_sync(0xffffffffu, dot, o);
        np  += __shfl_xor_sync(0xffffffffu, np,  o);
        nh  += __shfl_xor_sync(0xffffffffu, nh,  o);
    }
    if (lane == 0)
        d_x0[(size_t)warp * FIN] = 1.0f - dot / (sqrtf(np) * sqrtf(nh));
}

// ---------------------------------------------------------------------------
// BatchNorm stats -> folded scale/shift
// ---------------------------------------------------------------------------
__global__ void bn_stats_kernel(int which, const float* __restrict__ gamma,
                                const float* __restrict__ beta, int M, int F)
{
    const float* x = (which == 0) ? d_x0 : (which == 1) ? d_x1 : d_x2;
    __shared__ float s1[8][33];
    int fl = threadIdx.x & 31;
    int f  = blockIdx.x * 32 + fl;
    int rl = threadIdx.x >> 5;

    float s = 0;
    if (f < F) for (int r = rl; r < M; r += 8) s += x[(size_t)r * F + f];
    s1[rl][fl] = s;
    __syncthreads();
    if (rl == 0) {
        float t = 0;
        #pragma unroll
        for (int i = 0; i < 8; i++) t += s1[i][fl];
        s1[0][fl] = t / (float)M;
    }
    __syncthreads();
    float mean = s1[0][fl];
    __syncthreads();

    float v = 0;
    if (f < F) for (int r = rl; r < M; r += 8) {
        float d = x[(size_t)r * F + f] - mean;
        v += d * d;
    }
    s1[rl][fl] = v;
    __syncthreads();
    if (rl == 0 && f < F) {
        float t = 0;
        #pragma unroll
        for (int i = 0; i < 8; i++) t += s1[i][fl];
        float rstd = rsqrtf(t / (float)M + 1e-5f);
        float sc = rstd * gamma[f];
        d_scale[f] = sc;
        d_shift[f] = beta[f] - mean * sc;
    }
}

// ---------------------------------------------------------------------------
// Convert BN(x) to fp16 hi/lo planes [BATCH][KP2]
// ---------------------------------------------------------------------------
__global__ void __launch_bounds__(256) bnconv_kernel(int which)
{
    const float* x = (which == 0) ? d_x0 : (which == 1) ? d_x1 : d_x2;
    int idx = blockIdx.x * 256 + threadIdx.x;
    if (idx >= BATCH * KP2) return;
    int m = idx / KP2, k = idx - m * KP2;
    float y = 0.0f;
    if (k < FIN) y = x[(size_t)m * FIN + k] * d_scale[k] + d_shift[k];
    __half hi = __float2half_rn(y);
    d_mAhi[idx] = hi;
    d_mAlo[idx] = __float2half_rn(y - __half2float(hi));
}

// ---------------------------------------------------------------------------
// MLP hidden layer: out = relu( BN(x) @ W^T + bl ) via fp16 3-product mma.
// ---------------------------------------------------------------------------
__global__ void __launch_bounds__(256, 3) mlp_mma_kernel(
    int layer, const float* __restrict__ bl)
{
    extern __shared__ char smem[];
    uint32_t sbase = smem_u32(smem);
    int tid = threadIdx.x;
    int wid = tid >> 5, lane = tid & 31;
    int wm = wid >> 2, wn = wid & 3;
    int bn = blockIdx.x * BN;
    int bm = blockIdx.y * BM;

    const __half* Whi = layer ? d_W1hi : d_W0hi;
    const __half* Wlo = layer ? d_W1lo : d_W0lo;
    float* out = layer ? d_x2 : d_x1;

    float acc[2][4][4] = {};

    // chunk c: 0..16 Ahi*Whi, 17..33 Ahi*Wlo, 34..50 Alo*Whi
    auto issue_chunk = [&](int c, int stage) {
        const __half* A = (c < 34) ? d_mAhi : d_mAlo;
        const __half* B = (c >= 17 && c < 34) ? Wlo : Whi;
        int kc = (c < 17) ? c : (c < 34) ? c - 17 : c - 34;
        uint32_t sA = sbase + stage * STAGE_BYTES;
        uint32_t sB = sA + A_BYTES;
        load_tileA(sA, A, bm, kc * BK, KP2, tid);
        load_tileB(sB, B, bn, kc * BK, KP2, tid);
    };

    issue_chunk(0, 0); CP_COMMIT();
    issue_chunk(1, 1); CP_COMMIT();

    for (int c = 0; c < NMLP; c++) {
        CP_WAIT1();
        __syncthreads();
        int stage = c % NSTAGE;
        uint32_t sA = sbase + stage * STAGE_BYTES;
        uint32_t sB = sA + A_BYTES;

        #pragma unroll
        for (int ks = 0; ks < 4; ks++) {
            uint32_t a[2][4];
            #pragma unroll
            for (int mt = 0; mt < 2; mt++) {
                int row = wm * 32 + mt * 16 + (lane & 15);
                int c16 = ks * 2 + (lane >> 4);
                LDSM_X4(a[mt][0], a[mt][1], a[mt][2], a[mt][3], sA + swz(row, c16));
            }
            uint32_t b[4][2];
            #pragma unroll
            for (int nt2 = 0; nt2 < 2; nt2++) {
                int rown = wn * 32 + nt2 * 16 + (lane & 7) + (((lane >> 4) & 1) << 3);
                int c16 = ks * 2 + ((lane >> 3) & 1);
                uint32_t r0, r1, r2, r3;
                LDSM_X4(r0, r1, r2, r3, sB + swz(rown, c16));
                b[nt2 * 2][0] = r0;  b[nt2 * 2][1] = r1;
                b[nt2 * 2 + 1][0] = r2;  b[nt2 * 2 + 1][1] = r3;
            }
            #pragma unroll
            for (int mt = 0; mt < 2; mt++)
                #pragma unroll
                for (int nt = 0; nt < 4; nt++)
                    mma16816(acc[mt][nt], a[mt], b[nt]);
        }

        int nc = c + NSTAGE - 1;
        if (nc < NMLP) issue_chunk(nc, nc % NSTAGE);
        CP_COMMIT();
    }

    // ---- write accs to SMEM ----
    __syncthreads();
    float* Cs = (float*)smem;          // [64][132]
    #pragma unroll
    for (int mt = 0; mt < 2; mt++)
        #pragma unroll
        for (int nt = 0; nt < 4; nt++) {
            int r = wm * 32 + mt * 16 + (lane >> 2);
            int col = wn * 32 + nt * 8 + (lane & 3) * 2;
            Cs[r * 132 + col]           = acc[mt][nt][0];
            Cs[r * 132 + col + 1]       = acc[mt][nt][1];
            Cs[(r + 8) * 132 + col]     = acc[mt][nt][2];
            Cs[(r + 8) * 132 + col + 1] = acc[mt][nt][3];
        }
    __syncthreads();

    // ---- bias + relu + store fp32 (guard n < FIN) ----
    #pragma unroll
    for (int i = 0; i < 8; i++) {
        int id = i * 256 + tid;
        int r = id >> 5, q = id & 31;
        int m = bm + r;
        int col = bn + q * 4;
        const float* cr = &Cs[r * 132 + q * 4];
        #pragma unroll
        for (int j = 0; j < 4; j++) {
            int n = col + j;
            if (n < FIN)
                out[(size_t)m * FIN + n] = fmaxf(cr[j] + bl[n], 0.0f);
        }
    }
}

__global__ void final_linear_kernel(const float* __restrict__ Wo,
                                    const float* __restrict__ blo,
                                    float* __restrict__ out)
{
    int m = blockIdx.x;
    int tid = threadIdx.x;  // 128
    float a0 = 0, a1 = 0, a2 = 0;
    for (int k = tid; k < FIN; k += 128) {
        float v = d_x2[(size_t)m * FIN + k] * d_scale[k] + d_shift[k];
        a0 += v * Wo[k];
        a1 += v * Wo[FIN + k];
        a2 += v * Wo[2 * FIN + k];
    }
    #pragma unroll
    for (int o = 16; o; o >>= 1) {
        a0 += __shfl_xor_sync(0xffffffffu, a0, o);
        a1 += __shfl_xor_sync(0xffffffffu, a1, o);
        a2 += __shfl_xor_sync(0xffffffffu, a2, o);
    }
    __shared__ float sm[3][4];
    int w = tid >> 5, lane = tid & 31;
    if (lane == 0) { sm[0][w] = a0; sm[1][w] = a1; sm[2][w] = a2; }
    __syncthreads();
    if (tid == 0) {
        out[m * 3 + 0] = sm[0][0] + sm[0][1] + sm[0][2] + sm[0][3] + blo[0];
        out[m * 3 + 1] = sm[1][0] + sm[1][1] + sm[1][2] + sm[1][3] + blo[1];
        out[m * 3 + 2] = sm[2][0] + sm[2][1] + sm[2][2] + sm[2][3] + blo[2];
    }
}

// ---------------------------------------------------------------------------
// Host launch
// ---------------------------------------------------------------------------
extern "C" void kernel_launch(void* const* d_in, const int* in_sizes, int n_in,
                              void* d_out, int out_size)
{
    const int*   prem  = (const int*)d_in[0];
    const int*   hyp   = (const int*)d_in[1];
    const float* embed = (const float*)d_in[2];
    const float* Wih   = (const float*)d_in[3];
    const float* Whh   = (const float*)d_in[4];
    const float* bih   = (const float*)d_in[5];
    const float* bhh   = (const float*)d_in[6];
    const float* g0  = (const float*)d_in[7];
    const float* be0 = (const float*)d_in[8];
    const float* W0  = (const float*)d_in[9];
    const float* bl0 = (const float*)d_in[10];
    const float* g1  = (const float*)d_in[11];
    const float* be1 = (const float*)d_in[12];
    const float* W1  = (const float*)d_in[13];
    const float* bl1 = (const float*)d_in[14];
    const float* go  = (const float*)d_in[15];
    const float* beo = (const float*)d_in[16];
    const float* Wo  = (const float*)d_in[17];
    const float* blo = (const float*)d_in[18];
    float* out = (float*)d_out;

    cudaFuncSetAttribute(lstm_mma_kernel,
                         cudaFuncAttributeMaxDynamicSharedMemorySize, SMEM_DYN);
    cudaFuncSetAttribute(mlp_mma_kernel,
                         cudaFuncAttributeMaxDynamicSharedMemorySize, SMEM_DYN);

    build_w_kernel<<<(NGATE * KPAD + 255) / 256, 256>>>(Wih, Whh, bih, bhh);
    build_mlp_w_kernel<<<(NPAD * KP2 + 255) / 256, 256>>>(W0, 0);
    build_mlp_w_kernel<<<(NPAD * KP2 + 255) / 256, 256>>>(W1, 1);
    zero_state_kernel<<<1024, 256>>>();

    // seed step-0 embeddings; steps 1..47 are gathered by the previous step's epilogue
    gather_kernel<<<(M2 * (DEMB / 4) + 255) / 256, 256>>>(embed, prem, hyp, 0, 0);

    for (int s = 0; s < SEQ; s++)
        lstm_mma_kernel<<<dim3(NGATE / BN, M2 / BM), 256, SMEM_DYN>>>(
            s & 1, s + 1, embed, prem, hyp);

    cosine_assemble_kernel<<<512, 256>>>();

    // MLP: (BN -> fp16 GEMM+ReLU) x2 -> BN -> fp32 final
    bn_stats_kernel<<<(FIN + 31) / 32, 256>>>(0, g0, be0, BATCH, FIN);
    bnconv_kernel<<<(BATCH * KP2 + 255) / 256, 256>>>(0);
    mlp_mma_kernel<<<dim3(NPAD / BN, BATCH / BM), 256, SMEM_DYN>>>(0, bl0);
    bn_stats_kernel<<<(FIN + 31) / 32, 256>>>(1, g1, be1, BATCH, FIN);
    bnconv_kernel<<<(BATCH * KP2 + 255) / 256, 256>>>(1);
    mlp_mma_kernel<<<dim3(NPAD / BN, BATCH / BM), 256, SMEM_DYN>>>(1, bl1);
    bn_stats_kernel<<<(FIN + 31) / 32, 256>>>(2, go, beo, BATCH, FIN);
    final_linear_kernel<<<BATCH, 128>>>(Wo, blo, out);
}

// round 16
// speedup vs baseline: 1.1982x; 1.0973x over previous
#include <cuda_runtime.h>
#include <cuda_fp16.h>
#include <cstdint>
#include <math.h>

// ---------------------------------------------------------------------------
// Model dims
// ---------------------------------------------------------------------------
#define BATCH 4096
#define SEQ   48
#define DEMB  300
#define DHID  512
#define NGATE 2048           // 4*DHID
#define KREAL 812            // DEMB + DHID
#define KPAD  832            // 13 chunks of 64
#define M2    8192           // 2*BATCH
#define FIN   1025           // 2*DHID + 1
#define DOUT  3

#define BK      64
#define NCHUNK  13           // KPAD/BK, single fp16 product
#define NSTAGE  3
#define BM      64
#define BN      128
#define A_BYTES 8192         // 64 rows x 128B
#define B_BYTES 16384        // 128 rows x 128B
#define STAGE_BYTES (A_BYTES + B_BYTES)       // 24576
#define SMEM_DYN   (NSTAGE * STAGE_BYTES)     // 73728

#define GY_COMP (M2 / BM)    // 128 compute rows
#define GY_GATH 16           // 16 extra rows = 256 gather blocks
#define GY_TOT  (GY_COMP + GY_GATH)

// MLP dims (fp16 3-product path)
#define KP2    1088          // FIN padded to 17 chunks of 64
#define NMLP   51            // 3 plane-products
#define NPAD   1152          // 9 * BN (N=1025 padded)

// ---------------------------------------------------------------------------
// Device scratch (static only)
// ---------------------------------------------------------------------------
__device__ __half d_X[2][(size_t)M2 * KPAD];
__device__ __half d_W[(size_t)NGATE * KPAD];
__device__ float d_bias[NGATE];
__device__ float d_cbuf[(size_t)M2 * DHID];
__device__ float d_x0[BATCH * FIN];
__device__ float d_x1[BATCH * FIN];
__device__ float d_x2[BATCH * FIN];
__device__ float d_scale[FIN];
__device__ float d_shift[FIN];
// MLP fp16 planes
__device__ __half d_W0hi[(size_t)NPAD * KP2];
__device__ __half d_W0lo[(size_t)NPAD * KP2];
__device__ __half d_W1hi[(size_t)NPAD * KP2];
__device__ __half d_W1lo[(size_t)NPAD * KP2];
__device__ __half d_mAhi[(size_t)BATCH * KP2];
__device__ __half d_mAlo[(size_t)BATCH * KP2];

// ---------------------------------------------------------------------------
// PTX helpers
// ---------------------------------------------------------------------------
__device__ __forceinline__ uint32_t smem_u32(const void* p) {
    uint32_t a;
    asm("{ .reg .u64 t; cvta.to.shared.u64 t, %1; cvt.u32.u64 %0, t; }" : "=r"(a) : "l"(p));
    return a;
}
__device__ __forceinline__ void cp16(uint32_t s, const void* g) {
    asm volatile("cp.async.cg.shared.global [%0], [%1], 16;" :: "r"(s), "l"(g));
}
#define CP_COMMIT() asm volatile("cp.async.commit_group;" ::: "memory")
#define CP_WAIT1()  asm volatile("cp.async.wait_group 1;" ::: "memory")

#define LDSM_X4(r0, r1, r2, r3, addr) \
    asm volatile("ldmatrix.sync.aligned.m8n8.x4.shared.b16 {%0,%1,%2,%3}, [%4];" \
        : "=r"(r0), "=r"(r1), "=r"(r2), "=r"(r3) : "r"(addr))

__device__ __forceinline__ void mma16816(float c[4], const uint32_t a[4], const uint32_t b[2]) {
    asm volatile(
        "mma.sync.aligned.m16n8k16.row.col.f32.f16.f16.f32 "
        "{%0,%1,%2,%3}, {%4,%5,%6,%7}, {%8,%9}, {%0,%1,%2,%3};"
        : "+f"(c[0]), "+f"(c[1]), "+f"(c[2]), "+f"(c[3])
        : "r"(a[0]), "r"(a[1]), "r"(a[2]), "r"(a[3]), "r"(b[0]), "r"(b[1]));
}

// swizzled byte offset within a [rows x 64 fp16] tile (128B rows)
__device__ __forceinline__ uint32_t swz(int row, int c16) {
    return (uint32_t)(row * 128 + ((c16 ^ (row & 7)) << 4));
}

__device__ __forceinline__ float sigmoidf_(float x) { return 1.0f / (1.0f + __expf(-x)); }
__device__ __forceinline__ float tanhf_(float x) {
    x = fminf(15.0f, fmaxf(-15.0f, x));
    float t = __expf(2.0f * x);
    return (t - 1.0f) / (t + 1.0f);
}

// ---------------------------------------------------------------------------
// Build W plane (gate-interleaved rows n'=4*hid+gate, fp16 rn) + bias
// ---------------------------------------------------------------------------
__global__ void __launch_bounds__(256) build_w_kernel(
    const float* __restrict__ Wih, const float* __restrict__ Whh,
    const float* __restrict__ bih, const float* __restrict__ bhh)
{
    int idx = blockIdx.x * 256 + threadIdx.x;
    if (idx >= NGATE * KPAD) return;
    int n = idx / KPAD, k = idx - n * KPAD;
    int gate = n & 3, hid = n >> 2;
    int no = gate * DHID + hid;
    float v = 0.0f;
    if (k < DEMB)       v = Wih[(size_t)no * DEMB + k];
    else if (k < KREAL) v = Whh[(size_t)no * DHID + (k - DEMB)];
    d_W[idx] = __float2half_rn(v);
    if (k == 0) d_bias[n] = bih[no] + bhh[no];
}

// ---------------------------------------------------------------------------
// Build MLP W hi/lo planes, padded [NPAD][KP2]
// ---------------------------------------------------------------------------
__global__ void __launch_bounds__(256) build_mlp_w_kernel(
    const float* __restrict__ W, int layer)
{
    int idx = blockIdx.x * 256 + threadIdx.x;
    if (idx >= NPAD * KP2) return;
    int n = idx / KP2, k = idx - n * KP2;
    float v = (n < FIN && k < FIN) ? W[(size_t)n * FIN + k] : 0.0f;
    __half hi = __float2half_rn(v);
    __half lo = __float2half_rn(v - __half2float(hi));
    if (layer == 0) { d_W0hi[idx] = hi; d_W0lo[idx] = lo; }
    else            { d_W1hi[idx] = hi; d_W1lo[idx] = lo; }
}

__global__ void zero_state_kernel()
{
    size_t stride = (size_t)gridDim.x * blockDim.x;
    size_t nX = (size_t)M2 * KPAD;
    __half z = __float2half_rn(0.0f);
    for (size_t j = blockIdx.x * (size_t)blockDim.x + threadIdx.x; j < nX; j += stride) {
        d_X[0][j] = z;
        d_X[1][j] = z;
    }
    for (size_t j = blockIdx.x * (size_t)blockDim.x + threadIdx.x; j < (size_t)M2 * DHID; j += stride)
        d_cbuf[j] = 0.0f;
}

// ---------------------------------------------------------------------------
// Embedding gather into X[par] cols [0,300) for one step (s=0 seed)
// ---------------------------------------------------------------------------
__global__ void __launch_bounds__(256) gather_kernel(
    const float* __restrict__ embed, const int* __restrict__ prem,
    const int* __restrict__ hyp, int s, int par)
{
    int idx = blockIdx.x * 256 + threadIdx.x;          // M2 * 75
    if (idx >= M2 * (DEMB / 4)) return;
    int row = idx / (DEMB / 4), k4 = idx - row * (DEMB / 4);
    int k = k4 * 4;
    int b = row & (BATCH - 1);
    int tok = (row < BATCH) ? prem[s * BATCH + b] : hyp[s * BATCH + b];
    float4 v = *reinterpret_cast<const float4*>(embed + (size_t)tok * DEMB + k);
    __half* xh = &d_X[par][(size_t)row * KPAD + k];
    xh[0] = __float2half_rn(v.x);
    xh[1] = __float2half_rn(v.y);
    xh[2] = __float2half_rn(v.z);
    xh[3] = __float2half_rn(v.w);
}

// ---------------------------------------------------------------------------
// LSTM step via mma.sync fp16 (single product) + fused cell epilogue.
// Tile 64x128, BK=64, 13 chunks, 3-stage cp.async, 3 CTAs/SM.
// Blocks with blockIdx.y >= GY_COMP are DEDICATED gather blocks: they write
// step-(s_next) embeddings into X[par^1] cols [0,300) — disjoint from this
// launch's compute reads (X[par]) and h-writes (cols 300..812 of X[par^1]).
// ---------------------------------------------------------------------------
__device__ __forceinline__ void load_tileA(uint32_t sbase, const __half* g,
                                           int row0, int k0, int rs, int tid)
{
    int r = tid >> 3;          // 0..31
    int c16 = tid & 7;
    const __half* gp = g + (size_t)(row0 + r) * rs + k0 + c16 * 8;
    #pragma unroll
    for (int p = 0; p < 2; p++)
        cp16(sbase + swz(r + p * 32, c16), gp + (size_t)(p * 32) * rs);
}
__device__ __forceinline__ void load_tileB(uint32_t sbase, const __half* g,
                                           int row0, int k0, int rs, int tid)
{
    int r = tid >> 3;
    int c16 = tid & 7;
    const __half* gp = g + (size_t)(row0 + r) * rs + k0 + c16 * 8;
    #pragma unroll
    for (int p = 0; p < 4; p++)
        cp16(sbase + swz(r + p * 32, c16), gp + (size_t)(p * 32) * rs);
}

__global__ void __launch_bounds__(256, 3) lstm_mma_kernel(
    int par, int s_next, const float* __restrict__ embed,
    const int* __restrict__ prem, const int* __restrict__ hyp)
{
    extern __shared__ char smem[];
    uint32_t sbase = smem_u32(smem);
    int tid = threadIdx.x;

    __half* X_w = d_X[par ^ 1];

    // ---- dedicated gather blocks ----
    if (blockIdx.y >= GY_COMP) {
        if (s_next < SEQ) {
            int gb = (blockIdx.y - GY_COMP) * 16 + blockIdx.x;   // 0..255
            const int NTH = GY_GATH * 16 * 256;                  // 65536
            for (int i = gb * 256 + tid; i < M2 * (DEMB / 4); i += NTH) {
                int row = i / (DEMB / 4), k4 = i - row * (DEMB / 4);
                int b = row & (BATCH - 1);
                int tok = (row < BATCH) ? prem[s_next * BATCH + b]
                                        : hyp[s_next * BATCH + b];
                float4 v = *reinterpret_cast<const float4*>(
                    embed + (size_t)tok * DEMB + k4 * 4);
                __half* xh = &X_w[(size_t)row * KPAD + k4 * 4];
                xh[0] = __float2half_rn(v.x);
                xh[1] = __float2half_rn(v.y);
                xh[2] = __float2half_rn(v.z);
                xh[3] = __float2half_rn(v.w);
            }
        }
        return;
    }

    int wid = tid >> 5, lane = tid & 31;
    int wm = wid >> 2, wn = wid & 3;          // 2 x 4 warp grid; warp tile 32x32
    int bn = blockIdx.x * BN;                 // N (gate) tile
    int bm = blockIdx.y * BM;                 // M (row) tile

    const __half* X_r = d_X[par];

    float acc[2][4][4] = {};

    auto issue_chunk = [&](int kc, int stage) {
        uint32_t sA = sbase + stage * STAGE_BYTES;
        uint32_t sB = sA + A_BYTES;
        load_tileA(sA, X_r, bm, kc * BK, KPAD, tid);
        load_tileB(sB, d_W, bn, kc * BK, KPAD, tid);
    };

    issue_chunk(0, 0); CP_COMMIT();
    issue_chunk(1, 1); CP_COMMIT();

    for (int c = 0; c < NCHUNK; c++) {
        CP_WAIT1();
        __syncthreads();
        int stage = c % NSTAGE;
        uint32_t sA = sbase + stage * STAGE_BYTES;
        uint32_t sB = sA + A_BYTES;

        #pragma unroll
        for (int ks = 0; ks < 4; ks++) {
            uint32_t a[2][4];
            #pragma unroll
            for (int mt = 0; mt < 2; mt++) {
                int row = wm * 32 + mt * 16 + (lane & 15);
                int c16 = ks * 2 + (lane >> 4);
                LDSM_X4(a[mt][0], a[mt][1], a[mt][2], a[mt][3], sA + swz(row, c16));
            }
            uint32_t b[4][2];
            #pragma unroll
            for (int nt2 = 0; nt2 < 2; nt2++) {
                int rown = wn * 32 + nt2 * 16 + (lane & 7) + (((lane >> 4) & 1) << 3);
                int c16 = ks * 2 + ((lane >> 3) & 1);
                uint32_t r0, r1, r2, r3;
                LDSM_X4(r0, r1, r2, r3, sB + swz(rown, c16));
                b[nt2 * 2][0] = r0;  b[nt2 * 2][1] = r1;
                b[nt2 * 2 + 1][0] = r2;  b[nt2 * 2 + 1][1] = r3;
            }
            #pragma unroll
            for (int mt = 0; mt < 2; mt++)
                #pragma unroll
                for (int nt = 0; nt < 4; nt++)
                    mma16816(acc[mt][nt], a[mt], b[nt]);
        }

        int nc = c + NSTAGE - 1;
        if (nc < NCHUNK) issue_chunk(nc, nc % NSTAGE);
        CP_COMMIT();
    }

    // ---- write accs to SMEM (reuse pipeline buffers) ----
    __syncthreads();
    float* Cs = (float*)smem;          // [64][132]
    #pragma unroll
    for (int mt = 0; mt < 2; mt++)
        #pragma unroll
        for (int nt = 0; nt < 4; nt++) {
            int r = wm * 32 + mt * 16 + (lane >> 2);
            int col = wn * 32 + nt * 8 + (lane & 3) * 2;
            Cs[r * 132 + col]           = acc[mt][nt][0];
            Cs[r * 132 + col + 1]       = acc[mt][nt][1];
            Cs[(r + 8) * 132 + col]     = acc[mt][nt][2];
            Cs[(r + 8) * 132 + col + 1] = acc[mt][nt][3];
        }
    __syncthreads();

    // ---- fused LSTM cell: 64 rows x 32 quads = 2048 items, 8 per thread ----
    #pragma unroll
    for (int i = 0; i < 8; i++) {
        int id = i * 256 + tid;
        int r = id >> 5, q = id & 31;
        int m = bm + r;
        int col = bn + q * 4;
        int hid = col >> 2;
        const float* cr = &Cs[r * 132 + q * 4];
        float ig = cr[0] + d_bias[col + 0];
        float fg = cr[1] + d_bias[col + 1];
        float gg = cr[2] + d_bias[col + 2];
        float og = cr[3] + d_bias[col + 3];
        size_t ci = (size_t)m * DHID + hid;
        float cn = sigmoidf_(fg) * d_cbuf[ci] + sigmoidf_(ig) * tanhf_(gg);
        float hn = sigmoidf_(og) * tanhf_(cn);
        d_cbuf[ci] = cn;
        X_w[(size_t)m * KPAD + DEMB + hid] = __float2half_rn(hn);
    }
}

// ---------------------------------------------------------------------------
// Cosine distance + assemble x0 = [dist, p, h] (reads X[0])
// ---------------------------------------------------------------------------
__global__ void cosine_assemble_kernel()
{
    int warp = (blockIdx.x * blockDim.x + threadIdx.x) >> 5;
    int lane = threadIdx.x & 31;
    if (warp >= BATCH) return;
    const __half* ph = d_X[0] + (size_t)warp * KPAD + DEMB;
    const __half* hh = d_X[0] + (size_t)(BATCH + warp) * KPAD + DEMB;
    float dot = 0, np = 0, nh = 0;
    for (int k = lane; k < DHID; k += 32) {
        float a = __half2float(ph[k]);
        float b = __half2float(hh[k]);
        dot += a * b; np += a * a; nh += b * b;
        d_x0[(size_t)warp * FIN + 1 + k]        = a;
        d_x0[(size_t)warp * FIN + 1 + DHID + k] = b;
    }
    #pragma unroll
    for (int o = 16; o; o >>= 1) {
        dot += __shfl_xor_sync(0xffffffffu, dot, o);
        np  += __shfl_xor_sync(0xffffffffu, np,  o);
        nh  += __shfl_xor_sync(0xffffffffu, nh,  o);
    }
    if (lane == 0)
        d_x0[(size_t)warp * FIN] = 1.0f - dot / (sqrtf(np) * sqrtf(nh));
}

// ---------------------------------------------------------------------------
// BatchNorm stats -> folded scale/shift
// ---------------------------------------------------------------------------
__global__ void bn_stats_kernel(int which, const float* __restrict__ gamma,
                                const float* __restrict__ beta, int M, int F)
{
    const float* x = (which == 0) ? d_x0 : (which == 1) ? d_x1 : d_x2;
    __shared__ float s1[8][33];
    int fl = threadIdx.x & 31;
    int f  = blockIdx.x * 32 + fl;
    int rl = threadIdx.x >> 5;

    float s = 0;
    if (f < F) for (int r = rl; r < M; r += 8) s += x[(size_t)r * F + f];
    s1[rl][fl] = s;
    __syncthreads();
    if (rl == 0) {
        float t = 0;
        #pragma unroll
        for (int i = 0; i < 8; i++) t += s1[i][fl];
        s1[0][fl] = t / (float)M;
    }
    __syncthreads();
    float mean = s1[0][fl];
    __syncthreads();

    float v = 0;
    if (f < F) for (int r = rl; r < M; r += 8) {
        float d = x[(size_t)r * F + f] - mean;
        v += d * d;
    }
    s1[rl][fl] = v;
    __syncthreads();
    if (rl == 0 && f < F) {
        float t = 0;
        #pragma unroll
        for (int i = 0; i < 8; i++) t += s1[i][fl];
        float rstd = rsqrtf(t / (float)M + 1e-5f);
        float sc = rstd * gamma[f];
        d_scale[f] = sc;
        d_shift[f] = beta[f] - mean * sc;
    }
}

// ---------------------------------------------------------------------------
// Convert BN(x) to fp16 hi/lo planes [BATCH][KP2]
// ---------------------------------------------------------------------------
__global__ void __launch_bounds__(256) bnconv_kernel(int which)
{
    const float* x = (which == 0) ? d_x0 : (which == 1) ? d_x1 : d_x2;
    int idx = blockIdx.x * 256 + threadIdx.x;
    if (idx >= BATCH * KP2) return;
    int m = idx / KP2, k = idx - m * KP2;
    float y = 0.0f;
    if (k < FIN) y = x[(size_t)m * FIN + k] * d_scale[k] + d_shift[k];
    __half hi = __float2half_rn(y);
    d_mAhi[idx] = hi;
    d_mAlo[idx] = __float2half_rn(y - __half2float(hi));
}

// ---------------------------------------------------------------------------
// MLP hidden layer: out = relu( BN(x) @ W^T + bl ) via fp16 3-product mma.
// ---------------------------------------------------------------------------
__global__ void __launch_bounds__(256, 3) mlp_mma_kernel(
    int layer, const float* __restrict__ bl)
{
    extern __shared__ char smem[];
    uint32_t sbase = smem_u32(smem);
    int tid = threadIdx.x;
    int wid = tid >> 5, lane = tid & 31;
    int wm = wid >> 2, wn = wid & 3;
    int bn = blockIdx.x * BN;
    int bm = blockIdx.y * BM;

    const __half* Whi = layer ? d_W1hi : d_W0hi;
    const __half* Wlo = layer ? d_W1lo : d_W0lo;
    float* out = layer ? d_x2 : d_x1;

    float acc[2][4][4] = {};

    // chunk c: 0..16 Ahi*Whi, 17..33 Ahi*Wlo, 34..50 Alo*Whi
    auto issue_chunk = [&](int c, int stage) {
        const __half* A = (c < 34) ? d_mAhi : d_mAlo;
        const __half* B = (c >= 17 && c < 34) ? Wlo : Whi;
        int kc = (c < 17) ? c : (c < 34) ? c - 17 : c - 34;
        uint32_t sA = sbase + stage * STAGE_BYTES;
        uint32_t sB = sA + A_BYTES;
        load_tileA(sA, A, bm, kc * BK, KP2, tid);
        load_tileB(sB, B, bn, kc * BK, KP2, tid);
    };

    issue_chunk(0, 0); CP_COMMIT();
    issue_chunk(1, 1); CP_COMMIT();

    for (int c = 0; c < NMLP; c++) {
        CP_WAIT1();
        __syncthreads();
        int stage = c % NSTAGE;
        uint32_t sA = sbase + stage * STAGE_BYTES;
        uint32_t sB = sA + A_BYTES;

        #pragma unroll
        for (int ks = 0; ks < 4; ks++) {
            uint32_t a[2][4];
            #pragma unroll
            for (int mt = 0; mt < 2; mt++) {
                int row = wm * 32 + mt * 16 + (lane & 15);
                int c16 = ks * 2 + (lane >> 4);
                LDSM_X4(a[mt][0], a[mt][1], a[mt][2], a[mt][3], sA + swz(row, c16));
            }
            uint32_t b[4][2];
            #pragma unroll
            for (int nt2 = 0; nt2 < 2; nt2++) {
                int rown = wn * 32 + nt2 * 16 + (lane & 7) + (((lane >> 4) & 1) << 3);
                int c16 = ks * 2 + ((lane >> 3) & 1);
                uint32_t r0, r1, r2, r3;
                LDSM_X4(r0, r1, r2, r3, sB + swz(rown, c16));
                b[nt2 * 2][0] = r0;  b[nt2 * 2][1] = r1;
                b[nt2 * 2 + 1][0] = r2;  b[nt2 * 2 + 1][1] = r3;
            }
            #pragma unroll
            for (int mt = 0; mt < 2; mt++)
                #pragma unroll
                for (int nt = 0; nt < 4; nt++)
                    mma16816(acc[mt][nt], a[mt], b[nt]);
        }

        int nc = c + NSTAGE - 1;
        if (nc < NMLP) issue_chunk(nc, nc % NSTAGE);
        CP_COMMIT();
    }

    // ---- write accs to SMEM ----
    __syncthreads();
    float* Cs = (float*)smem;          // [64][132]
    #pragma unroll
    for (int mt = 0; mt < 2; mt++)
        #pragma unroll
        for (int nt = 0; nt < 4; nt++) {
            int r = wm * 32 + mt * 16 + (lane >> 2);
            int col = wn * 32 + nt * 8 + (lane & 3) * 2;
            Cs[r * 132 + col]           = acc[mt][nt][0];
            Cs[r * 132 + col + 1]       = acc[mt][nt][1];
            Cs[(r + 8) * 132 + col]     = acc[mt][nt][2];
            Cs[(r + 8) * 132 + col + 1] = acc[mt][nt][3];
        }
    __syncthreads();

    // ---- bias + relu + store fp32 (guard n < FIN) ----
    #pragma unroll
    for (int i = 0; i < 8; i++) {
        int id = i * 256 + tid;
        int r = id >> 5, q = id & 31;
        int m = bm + r;
        int col = bn + q * 4;
        const float* cr = &Cs[r * 132 + q * 4];
        #pragma unroll
        for (int j = 0; j < 4; j++) {
            int n = col + j;
            if (n < FIN)
                out[(size_t)m * FIN + n] = fmaxf(cr[j] + bl[n], 0.0f);
        }
    }
}

__global__ void final_linear_kernel(const float* __restrict__ Wo,
                                    const float* __restrict__ blo,
                                    float* __restrict__ out)
{
    int m = blockIdx.x;
    int tid = threadIdx.x;  // 128
    float a0 = 0, a1 = 0, a2 = 0;
    for (int k = tid; k < FIN; k += 128) {
        float v = d_x2[(size_t)m * FIN + k] * d_scale[k] + d_shift[k];
        a0 += v * Wo[k];
        a1 += v * Wo[FIN + k];
        a2 += v * Wo[2 * FIN + k];
    }
    #pragma unroll
    for (int o = 16; o; o >>= 1) {
        a0 += __shfl_xor_sync(0xffffffffu, a0, o);
        a1 += __shfl_xor_sync(0xffffffffu, a1, o);
        a2 += __shfl_xor_sync(0xffffffffu, a2, o);
    }
    __shared__ float sm[3][4];
    int w = tid >> 5, lane = tid & 31;
    if (lane == 0) { sm[0][w] = a0; sm[1][w] = a1; sm[2][w] = a2; }
    __syncthreads();
    if (tid == 0) {
        out[m * 3 + 0] = sm[0][0] + sm[0][1] + sm[0][2] + sm[0][3] + blo[0];
        out[m * 3 + 1] = sm[1][0] + sm[1][1] + sm[1][2] + sm[1][3] + blo[1];
        out[m * 3 + 2] = sm[2][0] + sm[2][1] + sm[2][2] + sm[2][3] + blo[2];
    }
}

// ---------------------------------------------------------------------------
// Host launch
// ---------------------------------------------------------------------------
extern "C" void kernel_launch(void* const* d_in, const int* in_sizes, int n_in,
                              void* d_out, int out_size)
{
    const int*   prem  = (const int*)d_in[0];
    const int*   hyp   = (const int*)d_in[1];
    const float* embed = (const float*)d_in[2];
    const float* Wih   = (const float*)d_in[3];
    const float* Whh   = (const float*)d_in[4];
    const float* bih   = (const float*)d_in[5];
    const float* bhh   = (const float*)d_in[6];
    const float* g0  = (const float*)d_in[7];
    const float* be0 = (const float*)d_in[8];
    const float* W0  = (const float*)d_in[9];
    const float* bl0 = (const float*)d_in[10];
    const float* g1  = (const float*)d_in[11];
    const float* be1 = (const float*)d_in[12];
    const float* W1  = (const float*)d_in[13];
    const float* bl1 = (const float*)d_in[14];
    const float* go  = (const float*)d_in[15];
    const float* beo = (const float*)d_in[16];
    const float* Wo  = (const float*)d_in[17];
    const float* blo = (const float*)d_in[18];
    float* out = (float*)d_out;

    cudaFuncSetAttribute(lstm_mma_kernel,
                         cudaFuncAttributeMaxDynamicSharedMemorySize, SMEM_DYN);
    cudaFuncSetAttribute(mlp_mma_kernel,
                         cudaFuncAttributeMaxDynamicSharedMemorySize, SMEM_DYN);

    build_w_kernel<<<(NGATE * KPAD + 255) / 256, 256>>>(Wih, Whh, bih, bhh);
    build_mlp_w_kernel<<<(NPAD * KP2 + 255) / 256, 256>>>(W0, 0);
    build_mlp_w_kernel<<<(NPAD * KP2 + 255) / 256, 256>>>(W1, 1);
    zero_state_kernel<<<1024, 256>>>();

    // seed step-0 embeddings; steps 1..47 gathered by dedicated blocks
    gather_kernel<<<(M2 * (DEMB / 4) + 255) / 256, 256>>>(embed, prem, hyp, 0, 0);

    for (int s = 0; s < SEQ; s++)
        lstm_mma_kernel<<<dim3(NGATE / BN, GY_TOT), 256, SMEM_DYN>>>(
            s & 1, s + 1, embed, prem, hyp);

    cosine_assemble_kernel<<<512, 256>>>();

    // MLP: (BN -> fp16 GEMM+ReLU) x2 -> BN -> fp32 final
    bn_stats_kernel<<<(FIN + 31) / 32, 256>>>(0, g0, be0, BATCH, FIN);
    bnconv_kernel<<<(BATCH * KP2 + 255) / 256, 256>>>(0);
    mlp_mma_kernel<<<dim3(NPAD / BN, BATCH / BM), 256, SMEM_DYN>>>(0, bl0);
    bn_stats_kernel<<<(FIN + 31) / 32, 256>>>(1, g1, be1, BATCH, FIN);
    bnconv_kernel<<<(BATCH * KP2 + 255) / 256, 256>>>(1);
    mlp_mma_kernel<<<dim3(NPAD / BN, BATCH / BM), 256, SMEM_DYN>>>(1, bl1);
    bn_stats_kernel<<<(FIN + 31) / 32, 256>>>(2, go, beo, BATCH, FIN);
    final_linear_kernel<<<BATCH, 128>>>(Wo, blo, out);
}

// round 17
// speedup vs baseline: 1.2111x; 1.0108x over previous
#include <cuda_runtime.h>
#include <cuda_fp16.h>
#include <cstdint>
#include <math.h>

// ---------------------------------------------------------------------------
// Model dims
// ---------------------------------------------------------------------------
#define BATCH 4096
#define SEQ   48
#define DEMB  300
#define DHID  512
#define NGATE 2048           // 4*DHID
#define KREAL 812            // DEMB + DHID
#define KPAD  832            // 13 chunks of 64
#define M2    8192           // 2*BATCH
#define FIN   1025           // 2*DHID + 1
#define DOUT  3

#define BK      64
#define NCHUNK  13           // KPAD/BK, single fp16 product
#define NSTAGE  3
#define BM      64
#define BN      128
#define A_BYTES 8192         // 64 rows x 128B
#define B_BYTES 16384        // 128 rows x 128B
#define STAGE_BYTES (A_BYTES + B_BYTES)       // 24576
#define SMEM_DYN   (NSTAGE * STAGE_BYTES)     // 73728

#define GY_COMP (M2 / BM)    // 128 compute rows
#define GY_GATH 8            // 8 extra rows = 128 gather blocks (fits 5 waves)
#define GY_TOT  (GY_COMP + GY_GATH)

// MLP dims (fp16 2-product path: Ahi*Whi + Ahi*Wlo = Ahi*W)
#define KP2    1088          // FIN padded to 17 chunks of 64
#define NMLP   34            // 2 plane-products
#define NPAD   1152          // 9 * BN (N=1025 padded)

// ---------------------------------------------------------------------------
// Device scratch (static only)
// ---------------------------------------------------------------------------
__device__ __half d_X[2][(size_t)M2 * KPAD];
__device__ __half d_W[(size_t)NGATE * KPAD];
__device__ float d_bias[NGATE];
__device__ float d_cbuf[(size_t)M2 * DHID];
__device__ float d_x0[BATCH * FIN];
__device__ float d_x1[BATCH * FIN];
__device__ float d_x2[BATCH * FIN];
__device__ float d_scale[FIN];
__device__ float d_shift[FIN];
// MLP fp16 planes
__device__ __half d_W0hi[(size_t)NPAD * KP2];
__device__ __half d_W0lo[(size_t)NPAD * KP2];
__device__ __half d_W1hi[(size_t)NPAD * KP2];
__device__ __half d_W1lo[(size_t)NPAD * KP2];
__device__ __half d_mAhi[(size_t)BATCH * KP2];

// ---------------------------------------------------------------------------
// PTX helpers
// ---------------------------------------------------------------------------
__device__ __forceinline__ uint32_t smem_u32(const void* p) {
    uint32_t a;
    asm("{ .reg .u64 t; cvta.to.shared.u64 t, %1; cvt.u32.u64 %0, t; }" : "=r"(a) : "l"(p));
    return a;
}
__device__ __forceinline__ void cp16(uint32_t s, const void* g) {
    asm volatile("cp.async.cg.shared.global [%0], [%1], 16;" :: "r"(s), "l"(g));
}
#define CP_COMMIT() asm volatile("cp.async.commit_group;" ::: "memory")
#define CP_WAIT1()  asm volatile("cp.async.wait_group 1;" ::: "memory")

#define LDSM_X4(r0, r1, r2, r3, addr) \
    asm volatile("ldmatrix.sync.aligned.m8n8.x4.shared.b16 {%0,%1,%2,%3}, [%4];" \
        : "=r"(r0), "=r"(r1), "=r"(r2), "=r"(r3) : "r"(addr))

__device__ __forceinline__ void mma16816(float c[4], const uint32_t a[4], const uint32_t b[2]) {
    asm volatile(
        "mma.sync.aligned.m16n8k16.row.col.f32.f16.f16.f32 "
        "{%0,%1,%2,%3}, {%4,%5,%6,%7}, {%8,%9}, {%0,%1,%2,%3};"
        : "+f"(c[0]), "+f"(c[1]), "+f"(c[2]), "+f"(c[3])
        : "r"(a[0]), "r"(a[1]), "r"(a[2]), "r"(a[3]), "r"(b[0]), "r"(b[1]));
}

// swizzled byte offset within a [rows x 64 fp16] tile (128B rows)
__device__ __forceinline__ uint32_t swz(int row, int c16) {
    return (uint32_t)(row * 128 + ((c16 ^ (row & 7)) << 4));
}

__device__ __forceinline__ float sigmoidf_(float x) { return 1.0f / (1.0f + __expf(-x)); }
__device__ __forceinline__ float tanhf_(float x) {
    x = fminf(15.0f, fmaxf(-15.0f, x));
    float t = __expf(2.0f * x);
    return (t - 1.0f) / (t + 1.0f);
}

// ---------------------------------------------------------------------------
// Build W plane (gate-interleaved rows n'=4*hid+gate, fp16 rn) + bias
// ---------------------------------------------------------------------------
__global__ void __launch_bounds__(256) build_w_kernel(
    const float* __restrict__ Wih, const float* __restrict__ Whh,
    const float* __restrict__ bih, const float* __restrict__ bhh)
{
    int idx = blockIdx.x * 256 + threadIdx.x;
    if (idx >= NGATE * KPAD) return;
    int n = idx / KPAD, k = idx - n * KPAD;
    int gate = n & 3, hid = n >> 2;
    int no = gate * DHID + hid;
    float v = 0.0f;
    if (k < DEMB)       v = Wih[(size_t)no * DEMB + k];
    else if (k < KREAL) v = Whh[(size_t)no * DHID + (k - DEMB)];
    d_W[idx] = __float2half_rn(v);
    if (k == 0) d_bias[n] = bih[no] + bhh[no];
}

// ---------------------------------------------------------------------------
// Build MLP W hi/lo planes, padded [NPAD][KP2]
// ---------------------------------------------------------------------------
__global__ void __launch_bounds__(256) build_mlp_w_kernel(
    const float* __restrict__ W, int layer)
{
    int idx = blockIdx.x * 256 + threadIdx.x;
    if (idx >= NPAD * KP2) return;
    int n = idx / KP2, k = idx - n * KP2;
    float v = (n < FIN && k < FIN) ? W[(size_t)n * FIN + k] : 0.0f;
    __half hi = __float2half_rn(v);
    __half lo = __float2half_rn(v - __half2float(hi));
    if (layer == 0) { d_W0hi[idx] = hi; d_W0lo[idx] = lo; }
    else            { d_W1hi[idx] = hi; d_W1lo[idx] = lo; }
}

__global__ void zero_state_kernel()
{
    size_t stride = (size_t)gridDim.x * blockDim.x;
    size_t nX = (size_t)M2 * KPAD;
    __half z = __float2half_rn(0.0f);
    for (size_t j = blockIdx.x * (size_t)blockDim.x + threadIdx.x; j < nX; j += stride) {
        d_X[0][j] = z;
        d_X[1][j] = z;
    }
    for (size_t j = blockIdx.x * (size_t)blockDim.x + threadIdx.x; j < (size_t)M2 * DHID; j += stride)
        d_cbuf[j] = 0.0f;
}

// ---------------------------------------------------------------------------
// Embedding gather into X[par] cols [0,300) for one step (s=0 seed)
// ---------------------------------------------------------------------------
__global__ void __launch_bounds__(256) gather_kernel(
    const float* __restrict__ embed, const int* __restrict__ prem,
    const int* __restrict__ hyp, int s, int par)
{
    int idx = blockIdx.x * 256 + threadIdx.x;          // M2 * 75
    if (idx >= M2 * (DEMB / 4)) return;
    int row = idx / (DEMB / 4), k4 = idx - row * (DEMB / 4);
    int k = k4 * 4;
    int b = row & (BATCH - 1);
    int tok = (row < BATCH) ? prem[s * BATCH + b] : hyp[s * BATCH + b];
    float4 v = *reinterpret_cast<const float4*>(embed + (size_t)tok * DEMB + k);
    __half* xh = &d_X[par][(size_t)row * KPAD + k];
    xh[0] = __float2half_rn(v.x);
    xh[1] = __float2half_rn(v.y);
    xh[2] = __float2half_rn(v.z);
    xh[3] = __float2half_rn(v.w);
}

// ---------------------------------------------------------------------------
// LSTM step via mma.sync fp16 (single product) + fused cell epilogue.
// Tile 64x128, BK=64, 13 chunks, 3-stage cp.async, 3 CTAs/SM.
// Blocks with blockIdx.y >= GY_COMP are DEDICATED gather blocks: they write
// step-(s_next) embeddings into X[par^1] cols [0,300) — disjoint from this
// launch's compute reads (X[par]) and h-writes (cols 300..812 of X[par^1]).
// ---------------------------------------------------------------------------
__device__ __forceinline__ void load_tileA(uint32_t sbase, const __half* g,
                                           int row0, int k0, int rs, int tid)
{
    int r = tid >> 3;          // 0..31
    int c16 = tid & 7;
    const __half* gp = g + (size_t)(row0 + r) * rs + k0 + c16 * 8;
    #pragma unroll
    for (int p = 0; p < 2; p++)
        cp16(sbase + swz(r + p * 32, c16), gp + (size_t)(p * 32) * rs);
}
__device__ __forceinline__ void load_tileB(uint32_t sbase, const __half* g,
                                           int row0, int k0, int rs, int tid)
{
    int r = tid >> 3;
    int c16 = tid & 7;
    const __half* gp = g + (size_t)(row0 + r) * rs + k0 + c16 * 8;
    #pragma unroll
    for (int p = 0; p < 4; p++)
        cp16(sbase + swz(r + p * 32, c16), gp + (size_t)(p * 32) * rs);
}

__global__ void __launch_bounds__(256, 3) lstm_mma_kernel(
    int par, int s_next, const float* __restrict__ embed,
    const int* __restrict__ prem, const int* __restrict__ hyp)
{
    extern __shared__ char smem[];
    uint32_t sbase = smem_u32(smem);
    int tid = threadIdx.x;

    __half* X_w = d_X[par ^ 1];

    // ---- dedicated gather blocks ----
    if (blockIdx.y >= GY_COMP) {
        if (s_next < SEQ) {
            int gb = (blockIdx.y - GY_COMP) * 16 + blockIdx.x;   // 0..127
            const int NTH = GY_GATH * 16 * 256;                  // 32768
            for (int i = gb * 256 + tid; i < M2 * (DEMB / 4); i += NTH) {
                int row = i / (DEMB / 4), k4 = i - row * (DEMB / 4);
                int b = row & (BATCH - 1);
                int tok = (row < BATCH) ? prem[s_next * BATCH + b]
                                        : hyp[s_next * BATCH + b];
                float4 v = *reinterpret_cast<const float4*>(
                    embed + (size_t)tok * DEMB + k4 * 4);
                __half* xh = &X_w[(size_t)row * KPAD + k4 * 4];
                xh[0] = __float2half_rn(v.x);
                xh[1] = __float2half_rn(v.y);
                xh[2] = __float2half_rn(v.z);
                xh[3] = __float2half_rn(v.w);
            }
        }
        return;
    }

    int wid = tid >> 5, lane = tid & 31;
    int wm = wid >> 2, wn = wid & 3;          // 2 x 4 warp grid; warp tile 32x32
    int bn = blockIdx.x * BN;                 // N (gate) tile
    int bm = blockIdx.y * BM;                 // M (row) tile

    const __half* X_r = d_X[par];

    float acc[2][4][4] = {};

    auto issue_chunk = [&](int kc, int stage) {
        uint32_t sA = sbase + stage * STAGE_BYTES;
        uint32_t sB = sA + A_BYTES;
        load_tileA(sA, X_r, bm, kc * BK, KPAD, tid);
        load_tileB(sB, d_W, bn, kc * BK, KPAD, tid);
    };

    issue_chunk(0, 0); CP_COMMIT();
    issue_chunk(1, 1); CP_COMMIT();

    for (int c = 0; c < NCHUNK; c++) {
        CP_WAIT1();
        __syncthreads();
        int stage = c % NSTAGE;
        uint32_t sA = sbase + stage * STAGE_BYTES;
        uint32_t sB = sA + A_BYTES;

        #pragma unroll
        for (int ks = 0; ks < 4; ks++) {
            uint32_t a[2][4];
            #pragma unroll
            for (int mt = 0; mt < 2; mt++) {
                int row = wm * 32 + mt * 16 + (lane & 15);
                int c16 = ks * 2 + (lane >> 4);
                LDSM_X4(a[mt][0], a[mt][1], a[mt][2], a[mt][3], sA + swz(row, c16));
            }
            uint32_t b[4][2];
            #pragma unroll
            for (int nt2 = 0; nt2 < 2; nt2++) {
                int rown = wn * 32 + nt2 * 16 + (lane & 7) + (((lane >> 4) & 1) << 3);
                int c16 = ks * 2 + ((lane >> 3) & 1);
                uint32_t r0, r1, r2, r3;
                LDSM_X4(r0, r1, r2, r3, sB + swz(rown, c16));
                b[nt2 * 2][0] = r0;  b[nt2 * 2][1] = r1;
                b[nt2 * 2 + 1][0] = r2;  b[nt2 * 2 + 1][1] = r3;
            }
            #pragma unroll
            for (int mt = 0; mt < 2; mt++)
                #pragma unroll
                for (int nt = 0; nt < 4; nt++)
                    mma16816(acc[mt][nt], a[mt], b[nt]);
        }

        int nc = c + NSTAGE - 1;
        if (nc < NCHUNK) issue_chunk(nc, nc % NSTAGE);
        CP_COMMIT();
    }

    // ---- write accs to SMEM (reuse pipeline buffers) ----
    __syncthreads();
    float* Cs = (float*)smem;          // [64][132]
    #pragma unroll
    for (int mt = 0; mt < 2; mt++)
        #pragma unroll
        for (int nt = 0; nt < 4; nt++) {
            int r = wm * 32 + mt * 16 + (lane >> 2);
            int col = wn * 32 + nt * 8 + (lane & 3) * 2;
            Cs[r * 132 + col]           = acc[mt][nt][0];
            Cs[r * 132 + col + 1]       = acc[mt][nt][1];
            Cs[(r + 8) * 132 + col]     = acc[mt][nt][2];
            Cs[(r + 8) * 132 + col + 1] = acc[mt][nt][3];
        }
    __syncthreads();

    // ---- fused LSTM cell: 64 rows x 32 quads = 2048 items, 8 per thread ----
    #pragma unroll
    for (int i = 0; i < 8; i++) {
        int id = i * 256 + tid;
        int r = id >> 5, q = id & 31;
        int m = bm + r;
        int col = bn + q * 4;
        int hid = col >> 2;
        const float* cr = &Cs[r * 132 + q * 4];
        float ig = cr[0] + d_bias[col + 0];
        float fg = cr[1] + d_bias[col + 1];
        float gg = cr[2] + d_bias[col + 2];
        float og = cr[3] + d_bias[col + 3];
        size_t ci = (size_t)m * DHID + hid;
        float cn = sigmoidf_(fg) * d_cbuf[ci] + sigmoidf_(ig) * tanhf_(gg);
        float hn = sigmoidf_(og) * tanhf_(cn);
        d_cbuf[ci] = cn;
        X_w[(size_t)m * KPAD + DEMB + hid] = __float2half_rn(hn);
    }
}

// ---------------------------------------------------------------------------
// Cosine distance + assemble x0 = [dist, p, h] (reads X[0])
// ---------------------------------------------------------------------------
__global__ void cosine_assemble_kernel()
{
    int warp = (blockIdx.x * blockDim.x + threadIdx.x) >> 5;
    int lane = threadIdx.x & 31;
    if (warp >= BATCH) return;
    const __half* ph = d_X[0] + (size_t)warp * KPAD + DEMB;
    const __half* hh = d_X[0] + (size_t)(BATCH + warp) * KPAD + DEMB;
    float dot = 0, np = 0, nh = 0;
    for (int k = lane; k < DHID; k += 32) {
        float a = __half2float(ph[k]);
        float b = __half2float(hh[k]);
        dot += a * b; np += a * a; nh += b * b;
        d_x0[(size_t)warp * FIN + 1 + k]        = a;
        d_x0[(size_t)warp * FIN + 1 + DHID + k] = b;
    }
    #pragma unroll
    for (int o = 16; o; o >>= 1) {
        dot += __shfl_xor_sync(0xffffffffu, dot, o);
        np  += __shfl_xor_sync(0xffffffffu, np,  o);
        nh  += __shfl_xor_sync(0xffffffffu, nh,  o);
    }
    if (lane == 0)
        d_x0[(size_t)warp * FIN] = 1.0f - dot / (sqrtf(np) * sqrtf(nh));
}

// ---------------------------------------------------------------------------
// BatchNorm stats -> folded scale/shift
// ---------------------------------------------------------------------------
__global__ void bn_stats_kernel(int which, const float* __restrict__ gamma,
                                const float* __restrict__ beta, int M, int F)
{
    const float* x = (which == 0) ? d_x0 : (which == 1) ? d_x1 : d_x2;
    __shared__ float s1[8][33];
    int fl = threadIdx.x & 31;
    int f  = blockIdx.x * 32 + fl;
    int rl = threadIdx.x >> 5;

    float s = 0;
    if (f < F) for (int r = rl; r < M; r += 8) s += x[(size_t)r * F + f];
    s1[rl][fl] = s;
    __syncthreads();
    if (rl == 0) {
        float t = 0;
        #pragma unroll
        for (int i = 0; i < 8; i++) t += s1[i][fl];
        s1[0][fl] = t / (float)M;
    }
    __syncthreads();
    float mean = s1[0][fl];
    __syncthreads();

    float v = 0;
    if (f < F) for (int r = rl; r < M; r += 8) {
        float d = x[(size_t)r * F + f] - mean;
        v += d * d;
    }
    s1[rl][fl] = v;
    __syncthreads();
    if (rl == 0 && f < F) {
        float t = 0;
        #pragma unroll
        for (int i = 0; i < 8; i++) t += s1[i][fl];
        float rstd = rsqrtf(t / (float)M + 1e-5f);
        float sc = rstd * gamma[f];
        d_scale[f] = sc;
        d_shift[f] = beta[f] - mean * sc;
    }
}

// ---------------------------------------------------------------------------
// Convert BN(x) to fp16 hi plane [BATCH][KP2]
// ---------------------------------------------------------------------------
__global__ void __launch_bounds__(256) bnconv_kernel(int which)
{
    const float* x = (which == 0) ? d_x0 : (which == 1) ? d_x1 : d_x2;
    int idx = blockIdx.x * 256 + threadIdx.x;
    if (idx >= BATCH * KP2) return;
    int m = idx / KP2, k = idx - m * KP2;
    float y = 0.0f;
    if (k < FIN) y = x[(size_t)m * FIN + k] * d_scale[k] + d_shift[k];
    d_mAhi[idx] = __float2half_rn(y);
}

// ---------------------------------------------------------------------------
// MLP hidden layer: out = relu( BN(x) @ W^T + bl ) via fp16 2-product mma
// (Ahi*Whi + Ahi*Wlo = Ahi*W exactly).
// ---------------------------------------------------------------------------
__global__ void __launch_bounds__(256, 3) mlp_mma_kernel(
    int layer, const float* __restrict__ bl)
{
    extern __shared__ char smem[];
    uint32_t sbase = smem_u32(smem);
    int tid = threadIdx.x;
    int wid = tid >> 5, lane = tid & 31;
    int wm = wid >> 2, wn = wid & 3;
    int bn = blockIdx.x * BN;
    int bm = blockIdx.y * BM;

    const __half* Whi = layer ? d_W1hi : d_W0hi;
    const __half* Wlo = layer ? d_W1lo : d_W0lo;
    float* out = layer ? d_x2 : d_x1;

    float acc[2][4][4] = {};

    // chunk c: 0..16 Ahi*Whi, 17..33 Ahi*Wlo
    auto issue_chunk = [&](int c, int stage) {
        const __half* B = (c >= 17) ? Wlo : Whi;
        int kc = (c < 17) ? c : c - 17;
        uint32_t sA = sbase + stage * STAGE_BYTES;
        uint32_t sB = sA + A_BYTES;
        load_tileA(sA, d_mAhi, bm, kc * BK, KP2, tid);
        load_tileB(sB, B, bn, kc * BK, KP2, tid);
    };

    issue_chunk(0, 0); CP_COMMIT();
    issue_chunk(1, 1); CP_COMMIT();

    for (int c = 0; c < NMLP; c++) {
        CP_WAIT1();
        __syncthreads();
        int stage = c % NSTAGE;
        uint32_t sA = sbase + stage * STAGE_BYTES;
        uint32_t sB = sA + A_BYTES;

        #pragma unroll
        for (int ks = 0; ks < 4; ks++) {
            uint32_t a[2][4];
            #pragma unroll
            for (int mt = 0; mt < 2; mt++) {
                int row = wm * 32 + mt * 16 + (lane & 15);
                int c16 = ks * 2 + (lane >> 4);
                LDSM_X4(a[mt][0], a[mt][1], a[mt][2], a[mt][3], sA + swz(row, c16));
            }
            uint32_t b[4][2];
            #pragma unroll
            for (int nt2 = 0; nt2 < 2; nt2++) {
                int rown = wn * 32 + nt2 * 16 + (lane & 7) + (((lane >> 4) & 1) << 3);
                int c16 = ks * 2 + ((lane >> 3) & 1);
                uint32_t r0, r1, r2, r3;
                LDSM_X4(r0, r1, r2, r3, sB + swz(rown, c16));
                b[nt2 * 2][0] = r0;  b[nt2 * 2][1] = r1;
                b[nt2 * 2 + 1][0] = r2;  b[nt2 * 2 + 1][1] = r3;
            }
            #pragma unroll
            for (int mt = 0; mt < 2; mt++)
                #pragma unroll
                for (int nt = 0; nt < 4; nt++)
                    mma16816(acc[mt][nt], a[mt], b[nt]);
        }

        int nc = c + NSTAGE - 1;
        if (nc < NMLP) issue_chunk(nc, nc % NSTAGE);
        CP_COMMIT();
    }

    // ---- write accs to SMEM ----
    __syncthreads();
    float* Cs = (float*)smem;          // [64][132]
    #pragma unroll
    for (int mt = 0; mt < 2; mt++)
        #pragma unroll
        for (int nt = 0; nt < 4; nt++) {
            int r = wm * 32 + mt * 16 + (lane >> 2);
            int col = wn * 32 + nt * 8 + (lane & 3) * 2;
            Cs[r * 132 + col]           = acc[mt][nt][0];
            Cs[r * 132 + col + 1]       = acc[mt][nt][1];
            Cs[(r + 8) * 132 + col]     = acc[mt][nt][2];
            Cs[(r + 8) * 132 + col + 1] = acc[mt][nt][3];
        }
    __syncthreads();

    // ---- bias + relu + store fp32 (guard n < FIN) ----
    #pragma unroll
    for (int i = 0; i < 8; i++) {
        int id = i * 256 + tid;
        int r = id >> 5, q = id & 31;
        int m = bm + r;
        int col = bn + q * 4;
        const float* cr = &Cs[r * 132 + q * 4];
        #pragma unroll
        for (int j = 0; j < 4; j++) {
            int n = col + j;
            if (n < FIN)
                out[(size_t)m * FIN + n] = fmaxf(cr[j] + bl[n], 0.0f);
        }
    }
}

__global__ void final_linear_kernel(const float* __restrict__ Wo,
                                    const float* __restrict__ blo,
                                    float* __restrict__ out)
{
    int m = blockIdx.x;
    int tid = threadIdx.x;  // 128
    float a0 = 0, a1 = 0, a2 = 0;
    for (int k = tid; k < FIN; k += 128) {
        float v = d_x2[(size_t)m * FIN + k] * d_scale[k] + d_shift[k];
        a0 += v * Wo[k];
        a1 += v * Wo[FIN + k];
        a2 += v * Wo[2 * FIN + k];
    }
    #pragma unroll
    for (int o = 16; o; o >>= 1) {
        a0 += __shfl_xor_sync(0xffffffffu, a0, o);
        a1 += __shfl_xor_sync(0xffffffffu, a1, o);
        a2 += __shfl_xor_sync(0xffffffffu, a2, o);
    }
    __shared__ float sm[3][4];
    int w = tid >> 5, lane = tid & 31;
    if (lane == 0) { sm[0][w] = a0; sm[1][w] = a1; sm[2][w] = a2; }
    __syncthreads();
    if (tid == 0) {
        out[m * 3 + 0] = sm[0][0] + sm[0][1] + sm[0][2] + sm[0][3] + blo[0];
        out[m * 3 + 1] = sm[1][0] + sm[1][1] + sm[1][2] + sm[1][3] + blo[1];
        out[m * 3 + 2] = sm[2][0] + sm[2][1] + sm[2][2] + sm[2][3] + blo[2];
    }
}

// ---------------------------------------------------------------------------
// Host launch
// ---------------------------------------------------------------------------
extern "C" void kernel_launch(void* const* d_in, const int* in_sizes, int n_in,
                              void* d_out, int out_size)
{
    const int*   prem  = (const int*)d_in[0];
    const int*   hyp   = (const int*)d_in[1];
    const float* embed = (const float*)d_in[2];
    const float* Wih   = (const float*)d_in[3];
    const float* Whh   = (const float*)d_in[4];
    const float* bih   = (const float*)d_in[5];
    const float* bhh   = (const float*)d_in[6];
    const float* g0  = (const float*)d_in[7];
    const float* be0 = (const float*)d_in[8];
    const float* W0  = (const float*)d_in[9];
    const float* bl0 = (const float*)d_in[10];
    const float* g1  = (const float*)d_in[11];
    const float* be1 = (const float*)d_in[12];
    const float* W1  = (const float*)d_in[13];
    const float* bl1 = (const float*)d_in[14];
    const float* go  = (const float*)d_in[15];
    const float* beo = (const float*)d_in[16];
    const float* Wo  = (const float*)d_in[17];
    const float* blo = (const float*)d_in[18];
    float* out = (float*)d_out;

    cudaFuncSetAttribute(lstm_mma_kernel,
                         cudaFuncAttributeMaxDynamicSharedMemorySize, SMEM_DYN);
    cudaFuncSetAttribute(mlp_mma_kernel,
                         cudaFuncAttributeMaxDynamicSharedMemorySize, SMEM_DYN);

    build_w_kernel<<<(NGATE * KPAD + 255) / 256, 256>>>(Wih, Whh, bih, bhh);
    build_mlp_w_kernel<<<(NPAD * KP2 + 255) / 256, 256>>>(W0, 0);
    build_mlp_w_kernel<<<(NPAD * KP2 + 255) / 256, 256>>>(W1, 1);
    zero_state_kernel<<<1024, 256>>>();

    // seed step-0 embeddings; steps 1..47 gathered by dedicated blocks
    gather_kernel<<<(M2 * (DEMB / 4) + 255) / 256, 256>>>(embed, prem, hyp, 0, 0);

    for (int s = 0; s < SEQ; s++)
        lstm_mma_kernel<<<dim3(NGATE / BN, GY_TOT), 256, SMEM_DYN>>>(
            s & 1, s + 1, embed, prem, hyp);

    cosine_assemble_kernel<<<512, 256>>>();

    // MLP: (BN -> fp16 GEMM+ReLU) x2 -> BN -> fp32 final
    bn_stats_kernel<<<(FIN + 31) / 32, 256>>>(0, g0, be0, BATCH, FIN);
    bnconv_kernel<<<(BATCH * KP2 + 255) / 256, 256>>>(0);
    mlp_mma_kernel<<<dim3(NPAD / BN, BATCH / BM), 256, SMEM_DYN>>>(0, bl0);
    bn_stats_kernel<<<(FIN + 31) / 32, 256>>>(1, g1, be1, BATCH, FIN);
    bnconv_kernel<<<(BATCH * KP2 + 255) / 256, 256>>>(1);
    mlp_mma_kernel<<<dim3(NPAD / BN, BATCH / BM), 256, SMEM_DYN>>>(1, bl1);
    bn_stats_kernel<<<(FIN + 31) / 32, 256>>>(2, go, beo, BATCH, FIN);
    final_linear_kernel<<<BATCH, 128>>>(Wo, blo, out);
}